// round 9
// baseline (speedup 1.0000x reference)
#include <cuda_runtime.h>
#include <cuda_fp16.h>
#include <math.h>
#include <stdint.h>

// ---------------- problem constants ----------------
#define TOK   4096
#define EMB   1024
#define NH    16
#define HD    64
#define SEQ   2048
#define MLP   4096
#define LN_EPS 1e-5f

// ---------------- scratch ----------------
static __device__ __half g_h16 [(size_t)TOK * EMB];
static __device__ __half g_qkv16[(size_t)TOK * 3 * EMB];
static __device__ __half g_o16 [(size_t)TOK * EMB];
static __device__ __half g_act16[(size_t)TOK * MLP];
static __device__ float  g_x1  [(size_t)TOK * EMB];
static __device__ __half g_wq16[(size_t)EMB * 3 * EMB];
static __device__ __half g_wp16[(size_t)EMB * EMB];
static __device__ __half g_w116[(size_t)EMB * MLP];
static __device__ __half g_w216[(size_t)MLP * EMB];

// ---------------- helpers ----------------
__device__ __forceinline__ uint32_t smem_u32(const void* p) {
    uint32_t a;
    asm("{ .reg .u64 t; cvta.to.shared.u64 t, %1; cvt.u32.u64 %0, t; }" : "=r"(a) : "l"(p));
    return a;
}
__device__ __forceinline__ void sts128(uint32_t addr, uint4 v) {
    asm volatile("st.shared.v4.b32 [%0], {%1, %2, %3, %4};"
        :: "r"(addr), "r"(v.x), "r"(v.y), "r"(v.z), "r"(v.w));
}
__device__ __forceinline__ uint32_t h2u(__half2 h) { return *(uint32_t*)&h; }
// 64B rows: 16B chunk bits [4:6) ^= (row>>1)&3
__device__ __forceinline__ uint32_t swz(uint32_t off) {
    return off ^ (((off >> 7) & 3u) << 4);
}
// 128B rows: 16B chunk bits [4:7) ^= row&7
__device__ __forceinline__ uint32_t sw128(uint32_t off) {
    return off ^ ((off >> 3) & 0x70u);
}
// 256B rows: 16B chunk bits [4:7) ^= row&7
__device__ __forceinline__ uint32_t sw256(uint32_t off) {
    return off ^ (((off >> 8) & 7u) << 4);
}
__device__ __forceinline__ void ldsm_x4(uint32_t addr, uint32_t* r) {
    asm volatile("ldmatrix.sync.aligned.m8n8.x4.shared.b16 {%0,%1,%2,%3}, [%4];"
        : "=r"(r[0]), "=r"(r[1]), "=r"(r[2]), "=r"(r[3]) : "r"(addr));
}
__device__ __forceinline__ void ldsm_x4_t(uint32_t addr, uint32_t* r) {
    asm volatile("ldmatrix.sync.aligned.m8n8.x4.trans.shared.b16 {%0,%1,%2,%3}, [%4];"
        : "=r"(r[0]), "=r"(r[1]), "=r"(r[2]), "=r"(r[3]) : "r"(addr));
}
__device__ __forceinline__ void mma16816(float* d, const uint32_t* a, const uint32_t* b) {
    asm volatile("mma.sync.aligned.m16n8k16.row.col.f32.f16.f16.f32 "
        "{%0,%1,%2,%3}, {%4,%5,%6,%7}, {%8,%9}, {%0,%1,%2,%3};"
        : "+f"(d[0]), "+f"(d[1]), "+f"(d[2]), "+f"(d[3])
        : "r"(a[0]), "r"(a[1]), "r"(a[2]), "r"(a[3]), "r"(b[0]), "r"(b[1]));
}
__device__ __forceinline__ void cpasync16(uint32_t saddr, const void* g) {
    asm volatile("cp.async.cg.shared.global [%0], [%1], 16;" :: "r"(saddr), "l"(g));
}
#define CP_COMMIT() asm volatile("cp.async.commit_group;" ::: "memory")
#define CP_WAIT2()  asm volatile("cp.async.wait_group 2;" ::: "memory")
#define CP_WAIT1()  asm volatile("cp.async.wait_group 1;" ::: "memory")
__device__ __forceinline__ float gelu_exact(float x) {
    return 0.5f * x * (1.f + erff(x * 0.70710678118654752f));
}

// =====================================================================
// fp32 -> fp16 weight conversion (single launch, all 4 weights)
// segments (blocks of 2048 elems): wq 1536 | wp 512 | w1 2048 | w2 2048
// =====================================================================
__global__ void f2h_all(const float* __restrict__ wq, __half* __restrict__ dq,
                        const float* __restrict__ wp, __half* __restrict__ dp,
                        const float* __restrict__ w1, __half* __restrict__ d1,
                        const float* __restrict__ w2, __half* __restrict__ d2)
{
    const int b = blockIdx.x;
    const float* src; __half* dst; int rb;
    if (b < 1536)      { src = wq; dst = dq; rb = b; }
    else if (b < 2048) { src = wp; dst = dp; rb = b - 1536; }
    else if (b < 4096) { src = w1; dst = d1; rb = b - 2048; }
    else               { src = w2; dst = d2; rb = b - 4096; }
    const int i = (rb * 256 + threadIdx.x) * 8;
    float4 a = *(const float4*)(src + i);
    float4 c = *(const float4*)(src + i + 4);
    uint4 o;
    o.x = h2u(__floats2half2_rn(a.x, a.y));
    o.y = h2u(__floats2half2_rn(a.z, a.w));
    o.z = h2u(__floats2half2_rn(c.x, c.y));
    o.w = h2u(__floats2half2_rn(c.z, c.w));
    *(uint4*)(dst + i) = o;
}

// =====================================================================
// HMMA GEMM, all-fp16 operands, cp.async 4-stage pipeline. (unchanged R7)
// Block 128x128, BK=32, 8 warps (2M x 4N) of 64x32.
// MODE: 0 = bias -> fp16 out, 1 = bias+gelu -> fp16 out, 2 = bias+res -> fp32 out
// =====================================================================
#define GEMM_SMEM (4 * 16384)

template<int MODE>
__global__ void __launch_bounds__(256, 2)
hgemm(const __half* __restrict__ A, const __half* __restrict__ B,
      const float* __restrict__ bias, const float* __restrict__ res,
      void* __restrict__ Cout, int M, int N, int K)
{
    extern __shared__ char dsm[];
    const uint32_t base = smem_u32(dsm);

    const int tid  = threadIdx.x;
    const int lane = tid & 31, wid = tid >> 5;
    const int wm = (wid & 1) * 64;
    const int wn = (wid >> 1) * 32;
    const int bm = blockIdx.y * 128, bn = blockIdx.x * 128;
    const int g = lane >> 3;

    float acc[4][4][4];
#pragma unroll
    for (int i = 0; i < 4; ++i)
#pragma unroll
        for (int j = 0; j < 4; ++j)
#pragma unroll
            for (int c = 0; c < 4; ++c) acc[i][j][c] = 0.f;

    const int nch = K / 32;

    auto issue = [&](int buf, int kc) {
        const uint32_t sA = base + buf * 16384u;
        const uint32_t sB = sA + 8192u;
#pragma unroll
        for (int i = 0; i < 2; ++i) {
            const int cc = tid * 2 + i;
            const int rowa = cc >> 2, kch = cc & 3;
            cpasync16(sA + swz((uint32_t)(rowa * 64 + kch * 16)),
                      A + (size_t)(bm + rowa) * K + kc * 32 + kch * 8);
            const int rowb = cc >> 4, nch2 = cc & 15;
            cpasync16(sB + sw256((uint32_t)(rowb * 256 + nch2 * 16)),
                      B + (size_t)(kc * 32 + rowb) * N + bn + nch2 * 8);
        }
    };

    auto compute = [&](int buf) {
        const uint32_t sA = base + buf * 16384u;
        const uint32_t sB = sA + 8192u;
#pragma unroll
        for (int ks = 0; ks < 2; ++ks) {
            uint32_t AF[4][4];
            const int ra = wm + (g & 1) * 8 + (lane & 7);
            const int ca = ks * 32 + (g >> 1) * 16;
#pragma unroll
            for (int mt = 0; mt < 4; ++mt)
                ldsm_x4(sA + swz((uint32_t)((ra + mt * 16) * 64 + ca)), AF[mt]);
            const int rb = ks * 16 + (g & 1) * 8 + (lane & 7);
#pragma unroll
            for (int p = 0; p < 2; ++p) {
                uint32_t t[4];
                const int cbb = (wn + p * 16) * 2 + (g >> 1) * 16;
                ldsm_x4_t(sB + sw256((uint32_t)(rb * 256 + cbb)), t);
#pragma unroll
                for (int mt = 0; mt < 4; ++mt) {
                    mma16816(acc[mt][p * 2 + 0], AF[mt], t);
                    mma16816(acc[mt][p * 2 + 1], AF[mt], t + 2);
                }
            }
        }
    };

    issue(0, 0); CP_COMMIT();
    issue(1, 1); CP_COMMIT();
    issue(2, 2); CP_COMMIT();

    for (int kc = 0; kc < nch; ++kc) {
        CP_WAIT2();
        __syncthreads();
        compute(kc & 3);
        if (kc + 3 < nch) issue((kc + 3) & 3, kc + 3);
        CP_COMMIT();
    }

#pragma unroll
    for (int mt = 0; mt < 4; ++mt) {
#pragma unroll
        for (int nt = 0; nt < 4; ++nt) {
            const int col = bn + wn + nt * 8 + (lane & 3) * 2;
            const float b0 = bias[col], b1 = bias[col + 1];
#pragma unroll
            for (int dp = 0; dp < 2; ++dp) {
                const int row = bm + wm + mt * 16 + (lane >> 2) + dp * 8;
                float o0 = acc[mt][nt][dp * 2 + 0] + b0;
                float o1 = acc[mt][nt][dp * 2 + 1] + b1;
                if (MODE == 1) { o0 = gelu_exact(o0); o1 = gelu_exact(o1); }
                if (MODE == 2) {
                    const float2 rv = *(const float2*)(res + (size_t)row * N + col);
                    float2 ov; ov.x = o0 + rv.x; ov.y = o1 + rv.y;
                    *(float2*)((float*)Cout + (size_t)row * N + col) = ov;
                } else {
                    *(__half2*)((__half*)Cout + (size_t)row * N + col) =
                        __floats2half2_rn(o0, o1);
                }
            }
        }
    }
}

// =====================================================================
// HMMA flash attention, fp16 in/out, cp.async double-buffered K/V.
// CTA = (b, head) x 128 queries, 256 threads; 8 warps (4 q-groups x 2 key-halves).
// smem: Q 16KB | 2 x (K 16KB + V 16KB) stages; Obuf fp32 aliases stage 0.
// =====================================================================
#define ATT_SMEM (16384 + 2 * 32768)

__global__ void __launch_bounds__(256, 1)
attn_mma(const __half* __restrict__ qkv, __half* __restrict__ o)
{
    extern __shared__ char dynsm[];
    __shared__ float smax[2][128];
    __shared__ float lsum2[2][128];

    const uint32_t Qb = smem_u32(dynsm);
    float* Obuf = (float*)(dynsm + 16384);   // aliases stage 0 after last compute

    const int tid  = threadIdx.x;
    const int lane = tid & 31, wid = tid >> 5;
    const int mg = wid >> 1, kh = wid & 1;
    const int b = blockIdx.x >> 4, hh = blockIdx.x & 15;
    const int q0 = blockIdx.y * 128;
    const size_t tb = (size_t)b * SEQ;
    const size_t RS = 3 * EMB;
    const unsigned FULL = 0xffffffffu;

    // ---- issue K/V tile kt into stage s (cp.async) ----
    auto issueKV = [&](int s, int kt) {
        const uint32_t Kb = Qb + 16384u + (uint32_t)s * 32768u;
        const uint32_t Vb = Kb + 16384u;
        const __half* kbase = qkv + (tb + kt * 128) * RS + EMB + hh * HD;
#pragma unroll
        for (int i = 0; i < 4; ++i) {
            const int cc = tid * 4 + i;          // 0..1023
            const int r = cc >> 3, ch = cc & 7;
            const uint32_t off = sw128((uint32_t)(r * 128 + ch * 16));
            cpasync16(Kb + off, kbase + (size_t)r * RS + ch * 8);
            cpasync16(Vb + off, kbase + EMB + (size_t)r * RS + ch * 8);
        }
    };

    // ---- load Q tile (scale by exact 0.125 in fp16) ----
    {
        const int r = tid >> 1, c0 = (tid & 1) * 32;
        const __half* qp = qkv + (tb + q0 + r) * RS + hh * HD + c0;
        const __half2 sc2 = __floats2half2_rn(0.125f, 0.125f);
#pragma unroll
        for (int j = 0; j < 4; ++j) {
            uint4 raw = *(const uint4*)(qp + j * 8);
            __half2* hp = (__half2*)&raw;
#pragma unroll
            for (int e = 0; e < 4; ++e) hp[e] = __hmul2(hp[e], sc2);
            sts128(Qb + sw128((uint32_t)(r * 128 + (c0 + j * 8) * 2)), raw);
        }
    }
    issueKV(0, 0); CP_COMMIT();
    __syncthreads();

    uint32_t QF[2][4][4];
    {
        const int g = lane >> 3;
#pragma unroll
        for (int mt = 0; mt < 2; ++mt)
#pragma unroll
            for (int t = 0; t < 4; ++t) {
                const int r = mg * 32 + mt * 16 + (g & 1) * 8 + (lane & 7);
                const int cb = t * 32 + (g >> 1) * 16;
                ldsm_x4(Qb + sw128((uint32_t)(r * 128 + cb)), QF[mt][t]);
            }
    }

    float Oa[2][8][4];
#pragma unroll
    for (int mt = 0; mt < 2; ++mt)
#pragma unroll
        for (int nt = 0; nt < 8; ++nt)
#pragma unroll
            for (int c = 0; c < 4; ++c) Oa[mt][nt][c] = 0.f;
    float m_run[4], l_run[4];
#pragma unroll
    for (int ri = 0; ri < 4; ++ri) { m_run[ri] = -INFINITY; l_run[ri] = 0.f; }

    for (int kt = 0; kt < SEQ / 128; ++kt) {
        __syncthreads();                          // prev compute done -> safe to overwrite
        if (kt + 1 < SEQ / 128) issueKV((kt + 1) & 1, kt + 1);
        CP_COMMIT();
        CP_WAIT1();                               // stage kt&1 complete
        __syncthreads();

        const uint32_t Kb = Qb + 16384u + (uint32_t)(kt & 1) * 32768u;
        const uint32_t Vb = Kb + 16384u;

        float sacc[2][8][4];
#pragma unroll
        for (int mt = 0; mt < 2; ++mt)
#pragma unroll
            for (int nt = 0; nt < 8; ++nt)
#pragma unroll
                for (int c = 0; c < 4; ++c) sacc[mt][nt][c] = 0.f;

        const int g = lane >> 3;
#pragma unroll
        for (int t = 0; t < 4; ++t) {
#pragma unroll
            for (int pr = 0; pr < 4; ++pr) {
                const int r = kh * 64 + pr * 16 + (g >> 1) * 8 + (lane & 7);
                const int cb = t * 32 + (g & 1) * 16;
                uint32_t tt[4];
                ldsm_x4(Kb + sw128((uint32_t)(r * 128 + cb)), tt);
#pragma unroll
                for (int mt = 0; mt < 2; ++mt) {
                    mma16816(sacc[mt][pr * 2 + 0], QF[mt][t], tt);
                    mma16816(sacc[mt][pr * 2 + 1], QF[mt][t], tt + 2);
                }
            }
        }

        float mloc[4];
#pragma unroll
        for (int ri = 0; ri < 4; ++ri) {
            const int mt = ri >> 1, h = ri & 1;
            float mx = sacc[mt][0][h * 2];
#pragma unroll
            for (int nt = 0; nt < 8; ++nt) {
                mx = fmaxf(mx, sacc[mt][nt][h * 2]);
                mx = fmaxf(mx, sacc[mt][nt][h * 2 + 1]);
            }
            mx = fmaxf(mx, __shfl_xor_sync(FULL, mx, 1));
            mx = fmaxf(mx, __shfl_xor_sync(FULL, mx, 2));
            mloc[ri] = mx;
        }
        if ((lane & 3) == 0) {
#pragma unroll
            for (int ri = 0; ri < 4; ++ri) {
                const int row = mg * 32 + (ri >> 1) * 16 + (ri & 1) * 8 + (lane >> 2);
                smax[kh][row] = mloc[ri];
            }
        }
        __syncthreads();

        float fexp[4];
#pragma unroll
        for (int ri = 0; ri < 4; ++ri) {
            const int row = mg * 32 + (ri >> 1) * 16 + (ri & 1) * 8 + (lane >> 2);
            const float mk = fmaxf(smax[0][row], smax[1][row]);
            const float mn = fmaxf(m_run[ri], mk);
            fexp[ri] = __expf(m_run[ri] - mn);
            m_run[ri] = mn;
            l_run[ri] *= fexp[ri];
        }
#pragma unroll
        for (int mt = 0; mt < 2; ++mt)
#pragma unroll
            for (int nt = 0; nt < 8; ++nt)
#pragma unroll
                for (int c = 0; c < 4; ++c) {
                    const int ri = mt * 2 + (c >> 1);
                    float p = __expf(sacc[mt][nt][c] - m_run[ri]);
                    sacc[mt][nt][c] = p;
                    l_run[ri] += p;
                }
#pragma unroll
        for (int mt = 0; mt < 2; ++mt)
#pragma unroll
            for (int nt = 0; nt < 8; ++nt)
#pragma unroll
                for (int c = 0; c < 4; ++c)
                    Oa[mt][nt][c] *= fexp[mt * 2 + (c >> 1)];

#pragma unroll
        for (int k2 = 0; k2 < 4; ++k2) {
            uint32_t pa[2][4];
#pragma unroll
            for (int mt = 0; mt < 2; ++mt) {
                pa[mt][0] = h2u(__floats2half2_rn(sacc[mt][2 * k2][0],     sacc[mt][2 * k2][1]));
                pa[mt][1] = h2u(__floats2half2_rn(sacc[mt][2 * k2][2],     sacc[mt][2 * k2][3]));
                pa[mt][2] = h2u(__floats2half2_rn(sacc[mt][2 * k2 + 1][0], sacc[mt][2 * k2 + 1][1]));
                pa[mt][3] = h2u(__floats2half2_rn(sacc[mt][2 * k2 + 1][2], sacc[mt][2 * k2 + 1][3]));
            }
#pragma unroll
            for (int npr = 0; npr < 4; ++npr) {
                const int r = kh * 64 + k2 * 16 + (g & 1) * 8 + (lane & 7);
                const int cb = npr * 32 + (g >> 1) * 16;
                uint32_t tt[4];
                ldsm_x4_t(Vb + sw128((uint32_t)(r * 128 + cb)), tt);
#pragma unroll
                for (int mt = 0; mt < 2; ++mt) {
                    mma16816(Oa[mt][npr * 2 + 0], pa[mt], tt);
                    mma16816(Oa[mt][npr * 2 + 1], pa[mt], tt + 2);
                }
            }
        }
    }

#pragma unroll
    for (int ri = 0; ri < 4; ++ri) {
        l_run[ri] += __shfl_xor_sync(FULL, l_run[ri], 1);
        l_run[ri] += __shfl_xor_sync(FULL, l_run[ri], 2);
    }
    if ((lane & 3) == 0) {
#pragma unroll
        for (int ri = 0; ri < 4; ++ri) {
            const int row = mg * 32 + (ri >> 1) * 16 + (ri & 1) * 8 + (lane >> 2);
            lsum2[kh][row] = l_run[ri];
        }
    }
    __syncthreads();   // all V reads done; Obuf may alias stage 0

    if (kh == 0) {
#pragma unroll
        for (int mt = 0; mt < 2; ++mt)
#pragma unroll
            for (int nt = 0; nt < 8; ++nt)
#pragma unroll
                for (int h = 0; h < 2; ++h) {
                    const int row = mg * 32 + mt * 16 + h * 8 + (lane >> 2);
                    const int col = nt * 8 + (lane & 3) * 2;
                    float2 v; v.x = Oa[mt][nt][h * 2]; v.y = Oa[mt][nt][h * 2 + 1];
                    *(float2*)&Obuf[row * 68 + col] = v;
                }
    }
    __syncthreads();
    if (kh == 1) {
#pragma unroll
        for (int mt = 0; mt < 2; ++mt)
#pragma unroll
            for (int h = 0; h < 2; ++h) {
                const int row = mg * 32 + mt * 16 + h * 8 + (lane >> 2);
                const float inv = 1.f / (lsum2[0][row] + lsum2[1][row]);
#pragma unroll
                for (int nt = 0; nt < 8; ++nt) {
                    const int col = nt * 8 + (lane & 3) * 2;
                    const float2 pv = *(const float2*)&Obuf[row * 68 + col];
                    *(__half2*)(o + (tb + q0 + row) * EMB + hh * HD + col) =
                        __floats2half2_rn((Oa[mt][nt][h * 2 + 0] + pv.x) * inv,
                                          (Oa[mt][nt][h * 2 + 1] + pv.y) * inv);
                }
            }
    }
}

// ---------------- LayerNorm: fp32 in -> fp16 out ----------------
__global__ void ln_kernel(const float* __restrict__ in, __half* __restrict__ out,
                          const float* __restrict__ gam, const float* __restrict__ bet)
{
    __shared__ float red[8], red2[8];
    __shared__ float s_mu, s_rstd;
    const int row = blockIdx.x;
    const float* x = in + (size_t)row * EMB;
    __half* y = out + (size_t)row * EMB;
    const int tid = threadIdx.x;

    float4 v = *(const float4*)(x + tid * 4);
    float s  = v.x + v.y + v.z + v.w;
    float sq = v.x * v.x + v.y * v.y + v.z * v.z + v.w * v.w;
    const unsigned FULL = 0xffffffffu;
#pragma unroll
    for (int o = 16; o > 0; o >>= 1) {
        s  += __shfl_down_sync(FULL, s, o);
        sq += __shfl_down_sync(FULL, sq, o);
    }
    int warp = tid >> 5, lane = tid & 31;
    if (lane == 0) { red[warp] = s; red2[warp] = sq; }
    __syncthreads();
    if (warp == 0) {
        s  = (lane < 8) ? red[lane]  : 0.f;
        sq = (lane < 8) ? red2[lane] : 0.f;
#pragma unroll
        for (int o = 4; o > 0; o >>= 1) {
            s  += __shfl_down_sync(FULL, s, o);
            sq += __shfl_down_sync(FULL, sq, o);
        }
        if (lane == 0) {
            float mu = s * (1.f / EMB);
            float var = sq * (1.f / EMB) - mu * mu;
            s_mu = mu; s_rstd = rsqrtf(var + LN_EPS);
        }
    }
    __syncthreads();
    const float mu = s_mu, rstd = s_rstd;
    const float4 g4 = *(const float4*)(gam + tid * 4);
    const float4 b4 = *(const float4*)(bet + tid * 4);
    __half2 h0 = __floats2half2_rn((v.x - mu) * rstd * g4.x + b4.x,
                                   (v.y - mu) * rstd * g4.y + b4.y);
    __half2 h1 = __floats2half2_rn((v.z - mu) * rstd * g4.z + b4.z,
                                   (v.w - mu) * rstd * g4.w + b4.w);
    uint2 pk; pk.x = h2u(h0); pk.y = h2u(h1);
    *(uint2*)(y + tid * 4) = pk;
}

// ---------------- launch ----------------
extern "C" void kernel_launch(void* const* d_in, const int* in_sizes, int n_in,
                              void* d_out, int out_size)
{
    const float* x      = (const float*)d_in[0];
    const float* ln1_g  = (const float*)d_in[1];
    const float* ln1_b  = (const float*)d_in[2];
    const float* ln2_g  = (const float*)d_in[3];
    const float* ln2_b  = (const float*)d_in[4];
    const float* w_qkv  = (const float*)d_in[5];
    const float* b_qkv  = (const float*)d_in[6];
    const float* w_proj = (const float*)d_in[7];
    const float* b_proj = (const float*)d_in[8];
    const float* w_fc1  = (const float*)d_in[9];
    const float* b_fc1  = (const float*)d_in[10];
    const float* w_fc2  = (const float*)d_in[11];
    const float* b_fc2  = (const float*)d_in[12];
    float* out = (float*)d_out;

    void *p_h16, *p_qkv16, *p_o16, *p_act16, *p_x1;
    void *p_wq, *p_wp, *p_w1, *p_w2;
    cudaGetSymbolAddress(&p_h16, g_h16);
    cudaGetSymbolAddress(&p_qkv16, g_qkv16);
    cudaGetSymbolAddress(&p_o16, g_o16);
    cudaGetSymbolAddress(&p_act16, g_act16);
    cudaGetSymbolAddress(&p_x1, g_x1);
    cudaGetSymbolAddress(&p_wq, g_wq16);
    cudaGetSymbolAddress(&p_wp, g_wp16);
    cudaGetSymbolAddress(&p_w1, g_w116);
    cudaGetSymbolAddress(&p_w2, g_w216);
    __half* h16   = (__half*)p_h16;
    __half* qkv16 = (__half*)p_qkv16;
    __half* o16   = (__half*)p_o16;
    __half* act16 = (__half*)p_act16;
    float*  x1    = (float*)p_x1;
    __half* wq16  = (__half*)p_wq;
    __half* wp16  = (__half*)p_wp;
    __half* w116  = (__half*)p_w1;
    __half* w216  = (__half*)p_w2;

    cudaFuncSetAttribute(hgemm<0>, cudaFuncAttributeMaxDynamicSharedMemorySize, GEMM_SMEM);
    cudaFuncSetAttribute(hgemm<1>, cudaFuncAttributeMaxDynamicSharedMemorySize, GEMM_SMEM);
    cudaFuncSetAttribute(hgemm<2>, cudaFuncAttributeMaxDynamicSharedMemorySize, GEMM_SMEM);
    cudaFuncSetAttribute(attn_mma, cudaFuncAttributeMaxDynamicSharedMemorySize, ATT_SMEM);

    // 0. weight conversion (fp32 -> fp16), one launch
    f2h_all<<<6144, 256>>>(w_qkv, wq16, w_proj, wp16, w_fc1, w116, w_fc2, w216);

    // 1. LN1 -> h16
    ln_kernel<<<TOK, 256>>>(x, h16, ln1_g, ln1_b);
    // 2. QKV (fp16 out)
    hgemm<0><<<dim3(3 * EMB / 128, TOK / 128), 256, GEMM_SMEM>>>(
        h16, wq16, b_qkv, nullptr, qkv16, TOK, 3 * EMB, EMB);
    // 3. attention (fp16 in/out)
    attn_mma<<<dim3(2 * NH, SEQ / 128), 256, ATT_SMEM>>>(qkv16, o16);
    // 4. proj + residual (fp32 out)
    hgemm<2><<<dim3(EMB / 128, TOK / 128), 256, GEMM_SMEM>>>(
        o16, wp16, b_proj, x, x1, TOK, EMB, EMB);
    // 5. LN2 -> h16
    ln_kernel<<<TOK, 256>>>(x1, h16, ln2_g, ln2_b);
    // 6. FC1 + GELU (fp16 out)
    hgemm<1><<<dim3(MLP / 128, TOK / 128), 256, GEMM_SMEM>>>(
        h16, w116, b_fc1, nullptr, act16, TOK, MLP, EMB);
    // 7. FC2 + residual (fp32 out)
    hgemm<2><<<dim3(EMB / 128, TOK / 128), 256, GEMM_SMEM>>>(
        act16, w216, b_fc2, x1, out, TOK, EMB, MLP);
}

// round 10
// speedup vs baseline: 1.0001x; 1.0001x over previous
#include <cuda_runtime.h>
#include <cuda_fp16.h>
#include <math.h>
#include <stdint.h>

// ---------------- problem constants ----------------
#define TOK   4096
#define EMB   1024
#define NH    16
#define HD    64
#define SEQ   2048
#define MLP   4096
#define LN_EPS 1e-5f

// ---------------- scratch ----------------
static __device__ __half g_h16 [(size_t)TOK * EMB];
static __device__ __half g_qkv16[(size_t)TOK * 3 * EMB];
static __device__ __half g_o16 [(size_t)TOK * EMB];
static __device__ __half g_act16[(size_t)TOK * MLP];
static __device__ float  g_x1  [(size_t)TOK * EMB];
static __device__ __half g_wq16[(size_t)EMB * 3 * EMB];
static __device__ __half g_wp16[(size_t)EMB * EMB];
static __device__ __half g_w116[(size_t)EMB * MLP];
static __device__ __half g_w216[(size_t)MLP * EMB];

// ---------------- helpers ----------------
__device__ __forceinline__ uint32_t smem_u32(const void* p) {
    uint32_t a;
    asm("{ .reg .u64 t; cvta.to.shared.u64 t, %1; cvt.u32.u64 %0, t; }" : "=r"(a) : "l"(p));
    return a;
}
__device__ __forceinline__ void sts128(uint32_t addr, uint4 v) {
    asm volatile("st.shared.v4.b32 [%0], {%1, %2, %3, %4};"
        :: "r"(addr), "r"(v.x), "r"(v.y), "r"(v.z), "r"(v.w));
}
__device__ __forceinline__ uint32_t h2u(__half2 h) { return *(uint32_t*)&h; }
// 64B rows: 16B chunk bits [4:6) ^= (row>>1)&3
__device__ __forceinline__ uint32_t swz(uint32_t off) {
    return off ^ (((off >> 7) & 3u) << 4);
}
// 128B rows: 16B chunk bits [4:7) ^= row&7
__device__ __forceinline__ uint32_t sw128(uint32_t off) {
    return off ^ ((off >> 3) & 0x70u);
}
// 256B rows: 16B chunk bits [4:7) ^= row&7
__device__ __forceinline__ uint32_t sw256(uint32_t off) {
    return off ^ (((off >> 8) & 7u) << 4);
}
__device__ __forceinline__ void ldsm_x4(uint32_t addr, uint32_t* r) {
    asm volatile("ldmatrix.sync.aligned.m8n8.x4.shared.b16 {%0,%1,%2,%3}, [%4];"
        : "=r"(r[0]), "=r"(r[1]), "=r"(r[2]), "=r"(r[3]) : "r"(addr));
}
__device__ __forceinline__ void ldsm_x4_t(uint32_t addr, uint32_t* r) {
    asm volatile("ldmatrix.sync.aligned.m8n8.x4.trans.shared.b16 {%0,%1,%2,%3}, [%4];"
        : "=r"(r[0]), "=r"(r[1]), "=r"(r[2]), "=r"(r[3]) : "r"(addr));
}
__device__ __forceinline__ void mma16816(float* d, const uint32_t* a, const uint32_t* b) {
    asm volatile("mma.sync.aligned.m16n8k16.row.col.f32.f16.f16.f32 "
        "{%0,%1,%2,%3}, {%4,%5,%6,%7}, {%8,%9}, {%0,%1,%2,%3};"
        : "+f"(d[0]), "+f"(d[1]), "+f"(d[2]), "+f"(d[3])
        : "r"(a[0]), "r"(a[1]), "r"(a[2]), "r"(a[3]), "r"(b[0]), "r"(b[1]));
}
__device__ __forceinline__ void cpasync16(uint32_t saddr, const void* g) {
    asm volatile("cp.async.cg.shared.global [%0], [%1], 16;" :: "r"(saddr), "l"(g));
}
#define CP_COMMIT() asm volatile("cp.async.commit_group;" ::: "memory")
#define CP_WAIT2()  asm volatile("cp.async.wait_group 2;" ::: "memory")
#define CP_WAIT1()  asm volatile("cp.async.wait_group 1;" ::: "memory")
__device__ __forceinline__ float gelu_exact(float x) {
    return 0.5f * x * (1.f + erff(x * 0.70710678118654752f));
}

// =====================================================================
// fp32 -> fp16 weight conversion (single launch, all 4 weights)
// segments (blocks of 2048 elems): wq 1536 | wp 512 | w1 2048 | w2 2048
// =====================================================================
__global__ void f2h_all(const float* __restrict__ wq, __half* __restrict__ dq,
                        const float* __restrict__ wp, __half* __restrict__ dp,
                        const float* __restrict__ w1, __half* __restrict__ d1,
                        const float* __restrict__ w2, __half* __restrict__ d2)
{
    const int b = blockIdx.x;
    const float* src; __half* dst; int rb;
    if (b < 1536)      { src = wq; dst = dq; rb = b; }
    else if (b < 2048) { src = wp; dst = dp; rb = b - 1536; }
    else if (b < 4096) { src = w1; dst = d1; rb = b - 2048; }
    else               { src = w2; dst = d2; rb = b - 4096; }
    const int i = (rb * 256 + threadIdx.x) * 8;
    float4 a = *(const float4*)(src + i);
    float4 c = *(const float4*)(src + i + 4);
    uint4 o;
    o.x = h2u(__floats2half2_rn(a.x, a.y));
    o.y = h2u(__floats2half2_rn(a.z, a.w));
    o.z = h2u(__floats2half2_rn(c.x, c.y));
    o.w = h2u(__floats2half2_rn(c.z, c.w));
    *(uint4*)(dst + i) = o;
}

// =====================================================================
// HMMA GEMM, all-fp16 operands, cp.async 4-stage pipeline. (unchanged R7)
// Block 128x128, BK=32, 8 warps (2M x 4N) of 64x32.
// MODE: 0 = bias -> fp16 out, 1 = bias+gelu -> fp16 out, 2 = bias+res -> fp32 out
// =====================================================================
#define GEMM_SMEM (4 * 16384)

template<int MODE>
__global__ void __launch_bounds__(256, 2)
hgemm(const __half* __restrict__ A, const __half* __restrict__ B,
      const float* __restrict__ bias, const float* __restrict__ res,
      void* __restrict__ Cout, int M, int N, int K)
{
    extern __shared__ char dsm[];
    const uint32_t base = smem_u32(dsm);

    const int tid  = threadIdx.x;
    const int lane = tid & 31, wid = tid >> 5;
    const int wm = (wid & 1) * 64;
    const int wn = (wid >> 1) * 32;
    const int bm = blockIdx.y * 128, bn = blockIdx.x * 128;
    const int g = lane >> 3;

    float acc[4][4][4];
#pragma unroll
    for (int i = 0; i < 4; ++i)
#pragma unroll
        for (int j = 0; j < 4; ++j)
#pragma unroll
            for (int c = 0; c < 4; ++c) acc[i][j][c] = 0.f;

    const int nch = K / 32;

    auto issue = [&](int buf, int kc) {
        const uint32_t sA = base + buf * 16384u;
        const uint32_t sB = sA + 8192u;
#pragma unroll
        for (int i = 0; i < 2; ++i) {
            const int cc = tid * 2 + i;
            const int rowa = cc >> 2, kch = cc & 3;
            cpasync16(sA + swz((uint32_t)(rowa * 64 + kch * 16)),
                      A + (size_t)(bm + rowa) * K + kc * 32 + kch * 8);
            const int rowb = cc >> 4, nch2 = cc & 15;
            cpasync16(sB + sw256((uint32_t)(rowb * 256 + nch2 * 16)),
                      B + (size_t)(kc * 32 + rowb) * N + bn + nch2 * 8);
        }
    };

    auto compute = [&](int buf) {
        const uint32_t sA = base + buf * 16384u;
        const uint32_t sB = sA + 8192u;
#pragma unroll
        for (int ks = 0; ks < 2; ++ks) {
            uint32_t AF[4][4];
            const int ra = wm + (g & 1) * 8 + (lane & 7);
            const int ca = ks * 32 + (g >> 1) * 16;
#pragma unroll
            for (int mt = 0; mt < 4; ++mt)
                ldsm_x4(sA + swz((uint32_t)((ra + mt * 16) * 64 + ca)), AF[mt]);
            const int rb = ks * 16 + (g & 1) * 8 + (lane & 7);
#pragma unroll
            for (int p = 0; p < 2; ++p) {
                uint32_t t[4];
                const int cbb = (wn + p * 16) * 2 + (g >> 1) * 16;
                ldsm_x4_t(sB + sw256((uint32_t)(rb * 256 + cbb)), t);
#pragma unroll
                for (int mt = 0; mt < 4; ++mt) {
                    mma16816(acc[mt][p * 2 + 0], AF[mt], t);
                    mma16816(acc[mt][p * 2 + 1], AF[mt], t + 2);
                }
            }
        }
    };

    issue(0, 0); CP_COMMIT();
    issue(1, 1); CP_COMMIT();
    issue(2, 2); CP_COMMIT();

    for (int kc = 0; kc < nch; ++kc) {
        CP_WAIT2();
        __syncthreads();
        compute(kc & 3);
        if (kc + 3 < nch) issue((kc + 3) & 3, kc + 3);
        CP_COMMIT();
    }

#pragma unroll
    for (int mt = 0; mt < 4; ++mt) {
#pragma unroll
        for (int nt = 0; nt < 4; ++nt) {
            const int col = bn + wn + nt * 8 + (lane & 3) * 2;
            const float b0 = bias[col], b1 = bias[col + 1];
#pragma unroll
            for (int dp = 0; dp < 2; ++dp) {
                const int row = bm + wm + mt * 16 + (lane >> 2) + dp * 8;
                float o0 = acc[mt][nt][dp * 2 + 0] + b0;
                float o1 = acc[mt][nt][dp * 2 + 1] + b1;
                if (MODE == 1) { o0 = gelu_exact(o0); o1 = gelu_exact(o1); }
                if (MODE == 2) {
                    const float2 rv = *(const float2*)(res + (size_t)row * N + col);
                    float2 ov; ov.x = o0 + rv.x; ov.y = o1 + rv.y;
                    *(float2*)((float*)Cout + (size_t)row * N + col) = ov;
                } else {
                    *(__half2*)((__half*)Cout + (size_t)row * N + col) =
                        __floats2half2_rn(o0, o1);
                }
            }
        }
    }
}

// =====================================================================
// HMMA flash attention, fp16 in/out, cp.async double-buffered K/V.
// CTA = (b, head) x 128 queries, 256 threads; 8 warps (4 q-groups x 2 key-halves).
// smem: Q 16KB | 2 x (K 16KB + V 16KB) stages; Obuf fp32 aliases stage 0.
// =====================================================================
#define ATT_SMEM (16384 + 2 * 32768)

__global__ void __launch_bounds__(256, 1)
attn_mma(const __half* __restrict__ qkv, __half* __restrict__ o)
{
    extern __shared__ char dynsm[];
    __shared__ float smax[2][128];
    __shared__ float lsum2[2][128];

    const uint32_t Qb = smem_u32(dynsm);
    float* Obuf = (float*)(dynsm + 16384);   // aliases stage 0 after last compute

    const int tid  = threadIdx.x;
    const int lane = tid & 31, wid = tid >> 5;
    const int mg = wid >> 1, kh = wid & 1;
    const int b = blockIdx.x >> 4, hh = blockIdx.x & 15;
    const int q0 = blockIdx.y * 128;
    const size_t tb = (size_t)b * SEQ;
    const size_t RS = 3 * EMB;
    const unsigned FULL = 0xffffffffu;

    // ---- issue K/V tile kt into stage s (cp.async) ----
    auto issueKV = [&](int s, int kt) {
        const uint32_t Kb = Qb + 16384u + (uint32_t)s * 32768u;
        const uint32_t Vb = Kb + 16384u;
        const __half* kbase = qkv + (tb + kt * 128) * RS + EMB + hh * HD;
#pragma unroll
        for (int i = 0; i < 4; ++i) {
            const int cc = tid * 4 + i;          // 0..1023
            const int r = cc >> 3, ch = cc & 7;
            const uint32_t off = sw128((uint32_t)(r * 128 + ch * 16));
            cpasync16(Kb + off, kbase + (size_t)r * RS + ch * 8);
            cpasync16(Vb + off, kbase + EMB + (size_t)r * RS + ch * 8);
        }
    };

    // ---- load Q tile (scale by exact 0.125 in fp16) ----
    {
        const int r = tid >> 1, c0 = (tid & 1) * 32;
        const __half* qp = qkv + (tb + q0 + r) * RS + hh * HD + c0;
        const __half2 sc2 = __floats2half2_rn(0.125f, 0.125f);
#pragma unroll
        for (int j = 0; j < 4; ++j) {
            uint4 raw = *(const uint4*)(qp + j * 8);
            __half2* hp = (__half2*)&raw;
#pragma unroll
            for (int e = 0; e < 4; ++e) hp[e] = __hmul2(hp[e], sc2);
            sts128(Qb + sw128((uint32_t)(r * 128 + (c0 + j * 8) * 2)), raw);
        }
    }
    issueKV(0, 0); CP_COMMIT();
    __syncthreads();

    uint32_t QF[2][4][4];
    {
        const int g = lane >> 3;
#pragma unroll
        for (int mt = 0; mt < 2; ++mt)
#pragma unroll
            for (int t = 0; t < 4; ++t) {
                const int r = mg * 32 + mt * 16 + (g & 1) * 8 + (lane & 7);
                const int cb = t * 32 + (g >> 1) * 16;
                ldsm_x4(Qb + sw128((uint32_t)(r * 128 + cb)), QF[mt][t]);
            }
    }

    float Oa[2][8][4];
#pragma unroll
    for (int mt = 0; mt < 2; ++mt)
#pragma unroll
        for (int nt = 0; nt < 8; ++nt)
#pragma unroll
            for (int c = 0; c < 4; ++c) Oa[mt][nt][c] = 0.f;
    float m_run[4], l_run[4];
#pragma unroll
    for (int ri = 0; ri < 4; ++ri) { m_run[ri] = -INFINITY; l_run[ri] = 0.f; }

    for (int kt = 0; kt < SEQ / 128; ++kt) {
        __syncthreads();                          // prev compute done -> safe to overwrite
        if (kt + 1 < SEQ / 128) issueKV((kt + 1) & 1, kt + 1);
        CP_COMMIT();
        CP_WAIT1();                               // stage kt&1 complete
        __syncthreads();

        const uint32_t Kb = Qb + 16384u + (uint32_t)(kt & 1) * 32768u;
        const uint32_t Vb = Kb + 16384u;

        float sacc[2][8][4];
#pragma unroll
        for (int mt = 0; mt < 2; ++mt)
#pragma unroll
            for (int nt = 0; nt < 8; ++nt)
#pragma unroll
                for (int c = 0; c < 4; ++c) sacc[mt][nt][c] = 0.f;

        const int g = lane >> 3;
#pragma unroll
        for (int t = 0; t < 4; ++t) {
#pragma unroll
            for (int pr = 0; pr < 4; ++pr) {
                const int r = kh * 64 + pr * 16 + (g >> 1) * 8 + (lane & 7);
                const int cb = t * 32 + (g & 1) * 16;
                uint32_t tt[4];
                ldsm_x4(Kb + sw128((uint32_t)(r * 128 + cb)), tt);
#pragma unroll
                for (int mt = 0; mt < 2; ++mt) {
                    mma16816(sacc[mt][pr * 2 + 0], QF[mt][t], tt);
                    mma16816(sacc[mt][pr * 2 + 1], QF[mt][t], tt + 2);
                }
            }
        }

        float mloc[4];
#pragma unroll
        for (int ri = 0; ri < 4; ++ri) {
            const int mt = ri >> 1, h = ri & 1;
            float mx = sacc[mt][0][h * 2];
#pragma unroll
            for (int nt = 0; nt < 8; ++nt) {
                mx = fmaxf(mx, sacc[mt][nt][h * 2]);
                mx = fmaxf(mx, sacc[mt][nt][h * 2 + 1]);
            }
            mx = fmaxf(mx, __shfl_xor_sync(FULL, mx, 1));
            mx = fmaxf(mx, __shfl_xor_sync(FULL, mx, 2));
            mloc[ri] = mx;
        }
        if ((lane & 3) == 0) {
#pragma unroll
            for (int ri = 0; ri < 4; ++ri) {
                const int row = mg * 32 + (ri >> 1) * 16 + (ri & 1) * 8 + (lane >> 2);
                smax[kh][row] = mloc[ri];
            }
        }
        __syncthreads();

        float fexp[4];
#pragma unroll
        for (int ri = 0; ri < 4; ++ri) {
            const int row = mg * 32 + (ri >> 1) * 16 + (ri & 1) * 8 + (lane >> 2);
            const float mk = fmaxf(smax[0][row], smax[1][row]);
            const float mn = fmaxf(m_run[ri], mk);
            fexp[ri] = __expf(m_run[ri] - mn);
            m_run[ri] = mn;
            l_run[ri] *= fexp[ri];
        }
#pragma unroll
        for (int mt = 0; mt < 2; ++mt)
#pragma unroll
            for (int nt = 0; nt < 8; ++nt)
#pragma unroll
                for (int c = 0; c < 4; ++c) {
                    const int ri = mt * 2 + (c >> 1);
                    float p = __expf(sacc[mt][nt][c] - m_run[ri]);
                    sacc[mt][nt][c] = p;
                    l_run[ri] += p;
                }
#pragma unroll
        for (int mt = 0; mt < 2; ++mt)
#pragma unroll
            for (int nt = 0; nt < 8; ++nt)
#pragma unroll
                for (int c = 0; c < 4; ++c)
                    Oa[mt][nt][c] *= fexp[mt * 2 + (c >> 1)];

#pragma unroll
        for (int k2 = 0; k2 < 4; ++k2) {
            uint32_t pa[2][4];
#pragma unroll
            for (int mt = 0; mt < 2; ++mt) {
                pa[mt][0] = h2u(__floats2half2_rn(sacc[mt][2 * k2][0],     sacc[mt][2 * k2][1]));
                pa[mt][1] = h2u(__floats2half2_rn(sacc[mt][2 * k2][2],     sacc[mt][2 * k2][3]));
                pa[mt][2] = h2u(__floats2half2_rn(sacc[mt][2 * k2 + 1][0], sacc[mt][2 * k2 + 1][1]));
                pa[mt][3] = h2u(__floats2half2_rn(sacc[mt][2 * k2 + 1][2], sacc[mt][2 * k2 + 1][3]));
            }
#pragma unroll
            for (int npr = 0; npr < 4; ++npr) {
                const int r = kh * 64 + k2 * 16 + (g & 1) * 8 + (lane & 7);
                const int cb = npr * 32 + (g >> 1) * 16;
                uint32_t tt[4];
                ldsm_x4_t(Vb + sw128((uint32_t)(r * 128 + cb)), tt);
#pragma unroll
                for (int mt = 0; mt < 2; ++mt) {
                    mma16816(Oa[mt][npr * 2 + 0], pa[mt], tt);
                    mma16816(Oa[mt][npr * 2 + 1], pa[mt], tt + 2);
                }
            }
        }
    }

#pragma unroll
    for (int ri = 0; ri < 4; ++ri) {
        l_run[ri] += __shfl_xor_sync(FULL, l_run[ri], 1);
        l_run[ri] += __shfl_xor_sync(FULL, l_run[ri], 2);
    }
    if ((lane & 3) == 0) {
#pragma unroll
        for (int ri = 0; ri < 4; ++ri) {
            const int row = mg * 32 + (ri >> 1) * 16 + (ri & 1) * 8 + (lane >> 2);
            lsum2[kh][row] = l_run[ri];
        }
    }
    __syncthreads();   // all V reads done; Obuf may alias stage 0

    if (kh == 0) {
#pragma unroll
        for (int mt = 0; mt < 2; ++mt)
#pragma unroll
            for (int nt = 0; nt < 8; ++nt)
#pragma unroll
                for (int h = 0; h < 2; ++h) {
                    const int row = mg * 32 + mt * 16 + h * 8 + (lane >> 2);
                    const int col = nt * 8 + (lane & 3) * 2;
                    float2 v; v.x = Oa[mt][nt][h * 2]; v.y = Oa[mt][nt][h * 2 + 1];
                    *(float2*)&Obuf[row * 68 + col] = v;
                }
    }
    __syncthreads();
    if (kh == 1) {
#pragma unroll
        for (int mt = 0; mt < 2; ++mt)
#pragma unroll
            for (int h = 0; h < 2; ++h) {
                const int row = mg * 32 + mt * 16 + h * 8 + (lane >> 2);
                const float inv = 1.f / (lsum2[0][row] + lsum2[1][row]);
#pragma unroll
                for (int nt = 0; nt < 8; ++nt) {
                    const int col = nt * 8 + (lane & 3) * 2;
                    const float2 pv = *(const float2*)&Obuf[row * 68 + col];
                    *(__half2*)(o + (tb + q0 + row) * EMB + hh * HD + col) =
                        __floats2half2_rn((Oa[mt][nt][h * 2 + 0] + pv.x) * inv,
                                          (Oa[mt][nt][h * 2 + 1] + pv.y) * inv);
                }
            }
    }
}

// ---------------- LayerNorm: fp32 in -> fp16 out ----------------
__global__ void ln_kernel(const float* __restrict__ in, __half* __restrict__ out,
                          const float* __restrict__ gam, const float* __restrict__ bet)
{
    __shared__ float red[8], red2[8];
    __shared__ float s_mu, s_rstd;
    const int row = blockIdx.x;
    const float* x = in + (size_t)row * EMB;
    __half* y = out + (size_t)row * EMB;
    const int tid = threadIdx.x;

    float4 v = *(const float4*)(x + tid * 4);
    float s  = v.x + v.y + v.z + v.w;
    float sq = v.x * v.x + v.y * v.y + v.z * v.z + v.w * v.w;
    const unsigned FULL = 0xffffffffu;
#pragma unroll
    for (int o = 16; o > 0; o >>= 1) {
        s  += __shfl_down_sync(FULL, s, o);
        sq += __shfl_down_sync(FULL, sq, o);
    }
    int warp = tid >> 5, lane = tid & 31;
    if (lane == 0) { red[warp] = s; red2[warp] = sq; }
    __syncthreads();
    if (warp == 0) {
        s  = (lane < 8) ? red[lane]  : 0.f;
        sq = (lane < 8) ? red2[lane] : 0.f;
#pragma unroll
        for (int o = 4; o > 0; o >>= 1) {
            s  += __shfl_down_sync(FULL, s, o);
            sq += __shfl_down_sync(FULL, sq, o);
        }
        if (lane == 0) {
            float mu = s * (1.f / EMB);
            float var = sq * (1.f / EMB) - mu * mu;
            s_mu = mu; s_rstd = rsqrtf(var + LN_EPS);
        }
    }
    __syncthreads();
    const float mu = s_mu, rstd = s_rstd;
    const float4 g4 = *(const float4*)(gam + tid * 4);
    const float4 b4 = *(const float4*)(bet + tid * 4);
    __half2 h0 = __floats2half2_rn((v.x - mu) * rstd * g4.x + b4.x,
                                   (v.y - mu) * rstd * g4.y + b4.y);
    __half2 h1 = __floats2half2_rn((v.z - mu) * rstd * g4.z + b4.z,
                                   (v.w - mu) * rstd * g4.w + b4.w);
    uint2 pk; pk.x = h2u(h0); pk.y = h2u(h1);
    *(uint2*)(y + tid * 4) = pk;
}

// ---------------- launch ----------------
extern "C" void kernel_launch(void* const* d_in, const int* in_sizes, int n_in,
                              void* d_out, int out_size)
{
    const float* x      = (const float*)d_in[0];
    const float* ln1_g  = (const float*)d_in[1];
    const float* ln1_b  = (const float*)d_in[2];
    const float* ln2_g  = (const float*)d_in[3];
    const float* ln2_b  = (const float*)d_in[4];
    const float* w_qkv  = (const float*)d_in[5];
    const float* b_qkv  = (const float*)d_in[6];
    const float* w_proj = (const float*)d_in[7];
    const float* b_proj = (const float*)d_in[8];
    const float* w_fc1  = (const float*)d_in[9];
    const float* b_fc1  = (const float*)d_in[10];
    const float* w_fc2  = (const float*)d_in[11];
    const float* b_fc2  = (const float*)d_in[12];
    float* out = (float*)d_out;

    void *p_h16, *p_qkv16, *p_o16, *p_act16, *p_x1;
    void *p_wq, *p_wp, *p_w1, *p_w2;
    cudaGetSymbolAddress(&p_h16, g_h16);
    cudaGetSymbolAddress(&p_qkv16, g_qkv16);
    cudaGetSymbolAddress(&p_o16, g_o16);
    cudaGetSymbolAddress(&p_act16, g_act16);
    cudaGetSymbolAddress(&p_x1, g_x1);
    cudaGetSymbolAddress(&p_wq, g_wq16);
    cudaGetSymbolAddress(&p_wp, g_wp16);
    cudaGetSymbolAddress(&p_w1, g_w116);
    cudaGetSymbolAddress(&p_w2, g_w216);
    __half* h16   = (__half*)p_h16;
    __half* qkv16 = (__half*)p_qkv16;
    __half* o16   = (__half*)p_o16;
    __half* act16 = (__half*)p_act16;
    float*  x1    = (float*)p_x1;
    __half* wq16  = (__half*)p_wq;
    __half* wp16  = (__half*)p_wp;
    __half* w116  = (__half*)p_w1;
    __half* w216  = (__half*)p_w2;

    cudaFuncSetAttribute(hgemm<0>, cudaFuncAttributeMaxDynamicSharedMemorySize, GEMM_SMEM);
    cudaFuncSetAttribute(hgemm<1>, cudaFuncAttributeMaxDynamicSharedMemorySize, GEMM_SMEM);
    cudaFuncSetAttribute(hgemm<2>, cudaFuncAttributeMaxDynamicSharedMemorySize, GEMM_SMEM);
    cudaFuncSetAttribute(attn_mma, cudaFuncAttributeMaxDynamicSharedMemorySize, ATT_SMEM);

    // 0. weight conversion (fp32 -> fp16), one launch
    f2h_all<<<6144, 256>>>(w_qkv, wq16, w_proj, wp16, w_fc1, w116, w_fc2, w216);

    // 1. LN1 -> h16
    ln_kernel<<<TOK, 256>>>(x, h16, ln1_g, ln1_b);
    // 2. QKV (fp16 out)
    hgemm<0><<<dim3(3 * EMB / 128, TOK / 128), 256, GEMM_SMEM>>>(
        h16, wq16, b_qkv, nullptr, qkv16, TOK, 3 * EMB, EMB);
    // 3. attention (fp16 in/out)
    attn_mma<<<dim3(2 * NH, SEQ / 128), 256, ATT_SMEM>>>(qkv16, o16);
    // 4. proj + residual (fp32 out)
    hgemm<2><<<dim3(EMB / 128, TOK / 128), 256, GEMM_SMEM>>>(
        o16, wp16, b_proj, x, x1, TOK, EMB, EMB);
    // 5. LN2 -> h16
    ln_kernel<<<TOK, 256>>>(x1, h16, ln2_g, ln2_b);
    // 6. FC1 + GELU (fp16 out)
    hgemm<1><<<dim3(MLP / 128, TOK / 128), 256, GEMM_SMEM>>>(
        h16, w116, b_fc1, nullptr, act16, TOK, MLP, EMB);
    // 7. FC2 + residual (fp32 out)
    hgemm<2><<<dim3(EMB / 128, TOK / 128), 256, GEMM_SMEM>>>(
        act16, w216, b_fc2, x1, out, TOK, EMB, MLP);
}

// round 11
// speedup vs baseline: 1.0348x; 1.0348x over previous
#include <cuda_runtime.h>
#include <cuda_fp16.h>
#include <math.h>
#include <stdint.h>

// ---------------- problem constants ----------------
#define TOK   4096
#define EMB   1024
#define NH    16
#define HD    64
#define SEQ   2048
#define MLP   4096
#define LN_EPS 1e-5f

// ---------------- scratch ----------------
static __device__ __half g_h16 [(size_t)TOK * EMB];
static __device__ __half g_qkv16[(size_t)TOK * 3 * EMB];
static __device__ __half g_o16 [(size_t)TOK * EMB];
static __device__ __half g_act16[(size_t)TOK * MLP];
static __device__ float  g_x1  [(size_t)TOK * EMB];
static __device__ __half g_wq16[(size_t)EMB * 3 * EMB];
static __device__ __half g_wp16[(size_t)EMB * EMB];
static __device__ __half g_w116[(size_t)EMB * MLP];
static __device__ __half g_w216[(size_t)MLP * EMB];

// ---------------- helpers ----------------
__device__ __forceinline__ uint32_t smem_u32(const void* p) {
    uint32_t a;
    asm("{ .reg .u64 t; cvta.to.shared.u64 t, %1; cvt.u32.u64 %0, t; }" : "=r"(a) : "l"(p));
    return a;
}
__device__ __forceinline__ void sts128(uint32_t addr, uint4 v) {
    asm volatile("st.shared.v4.b32 [%0], {%1, %2, %3, %4};"
        :: "r"(addr), "r"(v.x), "r"(v.y), "r"(v.z), "r"(v.w));
}
__device__ __forceinline__ uint32_t h2u(__half2 h) { return *(uint32_t*)&h; }
// 64B rows: 16B chunk bits [4:6) ^= (row>>1)&3
__device__ __forceinline__ uint32_t swz(uint32_t off) {
    return off ^ (((off >> 7) & 3u) << 4);
}
// 128B rows: 16B chunk bits [4:7) ^= row&7
__device__ __forceinline__ uint32_t sw128(uint32_t off) {
    return off ^ ((off >> 3) & 0x70u);
}
// 256B rows: 16B chunk bits [4:7) ^= row&7
__device__ __forceinline__ uint32_t sw256(uint32_t off) {
    return off ^ (((off >> 8) & 7u) << 4);
}
__device__ __forceinline__ void ldsm_x4(uint32_t addr, uint32_t* r) {
    asm volatile("ldmatrix.sync.aligned.m8n8.x4.shared.b16 {%0,%1,%2,%3}, [%4];"
        : "=r"(r[0]), "=r"(r[1]), "=r"(r[2]), "=r"(r[3]) : "r"(addr));
}
__device__ __forceinline__ void ldsm_x4_t(uint32_t addr, uint32_t* r) {
    asm volatile("ldmatrix.sync.aligned.m8n8.x4.trans.shared.b16 {%0,%1,%2,%3}, [%4];"
        : "=r"(r[0]), "=r"(r[1]), "=r"(r[2]), "=r"(r[3]) : "r"(addr));
}
__device__ __forceinline__ void mma16816(float* d, const uint32_t* a, const uint32_t* b) {
    asm volatile("mma.sync.aligned.m16n8k16.row.col.f32.f16.f16.f32 "
        "{%0,%1,%2,%3}, {%4,%5,%6,%7}, {%8,%9}, {%0,%1,%2,%3};"
        : "+f"(d[0]), "+f"(d[1]), "+f"(d[2]), "+f"(d[3])
        : "r"(a[0]), "r"(a[1]), "r"(a[2]), "r"(a[3]), "r"(b[0]), "r"(b[1]));
}
__device__ __forceinline__ void cpasync16(uint32_t saddr, const void* g) {
    asm volatile("cp.async.cg.shared.global [%0], [%1], 16;" :: "r"(saddr), "l"(g));
}
#define CP_COMMIT() asm volatile("cp.async.commit_group;" ::: "memory")
#define CP_WAIT2()  asm volatile("cp.async.wait_group 2;" ::: "memory")
#define CP_WAIT1()  asm volatile("cp.async.wait_group 1;" ::: "memory")
__device__ __forceinline__ float gelu_exact(float x) {
    return 0.5f * x * (1.f + erff(x * 0.70710678118654752f));
}

// =====================================================================
// fp32 -> fp16 weight conversion (single launch, all 4 weights)
// =====================================================================
__global__ void f2h_all(const float* __restrict__ wq, __half* __restrict__ dq,
                        const float* __restrict__ wp, __half* __restrict__ dp,
                        const float* __restrict__ w1, __half* __restrict__ d1,
                        const float* __restrict__ w2, __half* __restrict__ d2)
{
    const int b = blockIdx.x;
    const float* src; __half* dst; int rb;
    if (b < 1536)      { src = wq; dst = dq; rb = b; }
    else if (b < 2048) { src = wp; dst = dp; rb = b - 1536; }
    else if (b < 4096) { src = w1; dst = d1; rb = b - 2048; }
    else               { src = w2; dst = d2; rb = b - 4096; }
    const int i = (rb * 256 + threadIdx.x) * 8;
    float4 a = *(const float4*)(src + i);
    float4 c = *(const float4*)(src + i + 4);
    uint4 o;
    o.x = h2u(__floats2half2_rn(a.x, a.y));
    o.y = h2u(__floats2half2_rn(a.z, a.w));
    o.z = h2u(__floats2half2_rn(c.x, c.y));
    o.w = h2u(__floats2half2_rn(c.z, c.w));
    *(uint4*)(dst + i) = o;
}

// =====================================================================
// HMMA GEMM, all-fp16 operands, cp.async 4-stage pipeline. (unchanged)
// MODE: 0 = bias -> fp16, 1 = bias+gelu -> fp16, 2 = bias+res -> fp32
// =====================================================================
#define GEMM_SMEM (4 * 16384)

template<int MODE>
__global__ void __launch_bounds__(256, 2)
hgemm(const __half* __restrict__ A, const __half* __restrict__ B,
      const float* __restrict__ bias, const float* __restrict__ res,
      void* __restrict__ Cout, int M, int N, int K)
{
    extern __shared__ char dsm[];
    const uint32_t base = smem_u32(dsm);

    const int tid  = threadIdx.x;
    const int lane = tid & 31, wid = tid >> 5;
    const int wm = (wid & 1) * 64;
    const int wn = (wid >> 1) * 32;
    const int bm = blockIdx.y * 128, bn = blockIdx.x * 128;
    const int g = lane >> 3;

    float acc[4][4][4];
#pragma unroll
    for (int i = 0; i < 4; ++i)
#pragma unroll
        for (int j = 0; j < 4; ++j)
#pragma unroll
            for (int c = 0; c < 4; ++c) acc[i][j][c] = 0.f;

    const int nch = K / 32;

    auto issue = [&](int buf, int kc) {
        const uint32_t sA = base + buf * 16384u;
        const uint32_t sB = sA + 8192u;
#pragma unroll
        for (int i = 0; i < 2; ++i) {
            const int cc = tid * 2 + i;
            const int rowa = cc >> 2, kch = cc & 3;
            cpasync16(sA + swz((uint32_t)(rowa * 64 + kch * 16)),
                      A + (size_t)(bm + rowa) * K + kc * 32 + kch * 8);
            const int rowb = cc >> 4, nch2 = cc & 15;
            cpasync16(sB + sw256((uint32_t)(rowb * 256 + nch2 * 16)),
                      B + (size_t)(kc * 32 + rowb) * N + bn + nch2 * 8);
        }
    };

    auto compute = [&](int buf) {
        const uint32_t sA = base + buf * 16384u;
        const uint32_t sB = sA + 8192u;
#pragma unroll
        for (int ks = 0; ks < 2; ++ks) {
            uint32_t AF[4][4];
            const int ra = wm + (g & 1) * 8 + (lane & 7);
            const int ca = ks * 32 + (g >> 1) * 16;
#pragma unroll
            for (int mt = 0; mt < 4; ++mt)
                ldsm_x4(sA + swz((uint32_t)((ra + mt * 16) * 64 + ca)), AF[mt]);
            const int rb = ks * 16 + (g & 1) * 8 + (lane & 7);
#pragma unroll
            for (int p = 0; p < 2; ++p) {
                uint32_t t[4];
                const int cbb = (wn + p * 16) * 2 + (g >> 1) * 16;
                ldsm_x4_t(sB + sw256((uint32_t)(rb * 256 + cbb)), t);
#pragma unroll
                for (int mt = 0; mt < 4; ++mt) {
                    mma16816(acc[mt][p * 2 + 0], AF[mt], t);
                    mma16816(acc[mt][p * 2 + 1], AF[mt], t + 2);
                }
            }
        }
    };

    issue(0, 0); CP_COMMIT();
    issue(1, 1); CP_COMMIT();
    issue(2, 2); CP_COMMIT();

    for (int kc = 0; kc < nch; ++kc) {
        CP_WAIT2();
        __syncthreads();
        compute(kc & 3);
        if (kc + 3 < nch) issue((kc + 3) & 3, kc + 3);
        CP_COMMIT();
    }

#pragma unroll
    for (int mt = 0; mt < 4; ++mt) {
#pragma unroll
        for (int nt = 0; nt < 4; ++nt) {
            const int col = bn + wn + nt * 8 + (lane & 3) * 2;
            const float b0 = bias[col], b1 = bias[col + 1];
#pragma unroll
            for (int dp = 0; dp < 2; ++dp) {
                const int row = bm + wm + mt * 16 + (lane >> 2) + dp * 8;
                float o0 = acc[mt][nt][dp * 2 + 0] + b0;
                float o1 = acc[mt][nt][dp * 2 + 1] + b1;
                if (MODE == 1) { o0 = gelu_exact(o0); o1 = gelu_exact(o1); }
                if (MODE == 2) {
                    const float2 rv = *(const float2*)(res + (size_t)row * N + col);
                    float2 ov; ov.x = o0 + rv.x; ov.y = o1 + rv.y;
                    *(float2*)((float*)Cout + (size_t)row * N + col) = ov;
                } else {
                    *(__half2*)((__half*)Cout + (size_t)row * N + col) =
                        __floats2half2_rn(o0, o1);
                }
            }
        }
    }
}

// =====================================================================
// HMMA flash attention v2: warp-owns-rows layout.
// CTA = (b, head) x 128 queries, 256 threads; warp w owns q-rows [16w,16w+16),
// all keys. Key tile = 64, cp.async double-buffered.
// Softmax stats are pure intra-warp (quad shuffles) -> no smem exchange.
// smem: Q 16KB | 2 x (K 8KB + V 8KB) = 48KB.
// =====================================================================
#define ATT_SMEM (16384 + 2 * 16384)

__global__ void __launch_bounds__(256, 2)
attn_mma(const __half* __restrict__ qkv, __half* __restrict__ o)
{
    extern __shared__ char dynsm[];
    const uint32_t Qb = smem_u32(dynsm);

    const int tid  = threadIdx.x;
    const int lane = tid & 31, wid = tid >> 5;
    const int b = blockIdx.x >> 4, hh = blockIdx.x & 15;
    const int q0 = blockIdx.y * 128;
    const size_t tb = (size_t)b * SEQ;
    const size_t RS = 3 * EMB;
    const unsigned FULL = 0xffffffffu;
    const int g = lane >> 3;

    // ---- issue K/V tile kt (64 keys) into stage s ----
    auto issueKV = [&](int s, int kt) {
        const uint32_t Kb = Qb + 16384u + (uint32_t)s * 16384u;
        const uint32_t Vb = Kb + 8192u;
        const __half* kbase = qkv + (tb + kt * 64) * RS + EMB + hh * HD;
#pragma unroll
        for (int i = 0; i < 2; ++i) {
            const int cc = tid * 2 + i;          // 0..511
            const int r = cc >> 3, ch = cc & 7;
            const uint32_t off = sw128((uint32_t)(r * 128 + ch * 16));
            cpasync16(Kb + off, kbase + (size_t)r * RS + ch * 8);
            cpasync16(Vb + off, kbase + EMB + (size_t)r * RS + ch * 8);
        }
    };

    // ---- load Q tile (scale by exact 0.125 in fp16) ----
    {
        const int r = tid >> 1, c0 = (tid & 1) * 32;
        const __half* qp = qkv + (tb + q0 + r) * RS + hh * HD + c0;
        const __half2 sc2 = __floats2half2_rn(0.125f, 0.125f);
#pragma unroll
        for (int j = 0; j < 4; ++j) {
            uint4 raw = *(const uint4*)(qp + j * 8);
            __half2* hp = (__half2*)&raw;
#pragma unroll
            for (int e = 0; e < 4; ++e) hp[e] = __hmul2(hp[e], sc2);
            sts128(Qb + sw128((uint32_t)(r * 128 + (c0 + j * 8) * 2)), raw);
        }
    }
    issueKV(0, 0); CP_COMMIT();
    __syncthreads();

    // ---- preload Q fragments: warp's 16 rows ----
    uint32_t QF[4][4];
#pragma unroll
    for (int t = 0; t < 4; ++t) {
        const int r = wid * 16 + (g & 1) * 8 + (lane & 7);
        const int cb = t * 32 + (g >> 1) * 16;
        ldsm_x4(Qb + sw128((uint32_t)(r * 128 + cb)), QF[t]);
    }

    float Oa[8][4];
#pragma unroll
    for (int nt = 0; nt < 8; ++nt)
#pragma unroll
        for (int c = 0; c < 4; ++c) Oa[nt][c] = 0.f;
    float m_run[2] = {-INFINITY, -INFINITY};
    float l_run[2] = {0.f, 0.f};

    for (int kt = 0; kt < SEQ / 64; ++kt) {
        __syncthreads();                         // prev compute done
        if (kt + 1 < SEQ / 64) issueKV((kt + 1) & 1, kt + 1);
        CP_COMMIT();
        CP_WAIT1();
        __syncthreads();

        const uint32_t Kb = Qb + 16384u + (uint32_t)(kt & 1) * 16384u;
        const uint32_t Vb = Kb + 8192u;

        // ---- S = Q K^T : 16 rows x 64 keys ----
        float sacc[8][4];
#pragma unroll
        for (int nt = 0; nt < 8; ++nt)
#pragma unroll
            for (int c = 0; c < 4; ++c) sacc[nt][c] = 0.f;

#pragma unroll
        for (int t = 0; t < 4; ++t) {
#pragma unroll
            for (int pr = 0; pr < 4; ++pr) {
                const int r = pr * 16 + (g >> 1) * 8 + (lane & 7);
                const int cb = t * 32 + (g & 1) * 16;
                uint32_t tt[4];
                ldsm_x4(Kb + sw128((uint32_t)(r * 128 + cb)), tt);
                mma16816(sacc[pr * 2 + 0], QF[t], tt);
                mma16816(sacc[pr * 2 + 1], QF[t], tt + 2);
            }
        }

        // ---- online softmax (pure intra-warp) ----
        float fexp[2];
#pragma unroll
        for (int ri = 0; ri < 2; ++ri) {
            float mx = sacc[0][ri * 2];
#pragma unroll
            for (int nt = 0; nt < 8; ++nt) {
                mx = fmaxf(mx, sacc[nt][ri * 2]);
                mx = fmaxf(mx, sacc[nt][ri * 2 + 1]);
            }
            mx = fmaxf(mx, __shfl_xor_sync(FULL, mx, 1));
            mx = fmaxf(mx, __shfl_xor_sync(FULL, mx, 2));
            const float mn = fmaxf(m_run[ri], mx);
            fexp[ri] = __expf(m_run[ri] - mn);
            m_run[ri] = mn;
            l_run[ri] *= fexp[ri];
        }
#pragma unroll
        for (int nt = 0; nt < 8; ++nt)
#pragma unroll
            for (int c = 0; c < 4; ++c) {
                const int ri = c >> 1;
                float p = __expf(sacc[nt][c] - m_run[ri]);
                sacc[nt][c] = p;
                l_run[ri] += p;
            }
#pragma unroll
        for (int nt = 0; nt < 8; ++nt)
#pragma unroll
            for (int c = 0; c < 4; ++c)
                Oa[nt][c] *= fexp[c >> 1];

        // ---- O += P V ----
#pragma unroll
        for (int k2 = 0; k2 < 4; ++k2) {
            uint32_t pa[4];
            pa[0] = h2u(__floats2half2_rn(sacc[2 * k2][0],     sacc[2 * k2][1]));
            pa[1] = h2u(__floats2half2_rn(sacc[2 * k2][2],     sacc[2 * k2][3]));
            pa[2] = h2u(__floats2half2_rn(sacc[2 * k2 + 1][0], sacc[2 * k2 + 1][1]));
            pa[3] = h2u(__floats2half2_rn(sacc[2 * k2 + 1][2], sacc[2 * k2 + 1][3]));
#pragma unroll
            for (int npr = 0; npr < 4; ++npr) {
                const int r = k2 * 16 + (g & 1) * 8 + (lane & 7);
                const int cb = npr * 32 + (g >> 1) * 16;
                uint32_t tt[4];
                ldsm_x4_t(Vb + sw128((uint32_t)(r * 128 + cb)), tt);
                mma16816(Oa[npr * 2 + 0], pa, tt);
                mma16816(Oa[npr * 2 + 1], pa, tt + 2);
            }
        }
    }

    // ---- finalize: quad-reduce l, direct store ----
#pragma unroll
    for (int ri = 0; ri < 2; ++ri) {
        l_run[ri] += __shfl_xor_sync(FULL, l_run[ri], 1);
        l_run[ri] += __shfl_xor_sync(FULL, l_run[ri], 2);
    }
#pragma unroll
    for (int ri = 0; ri < 2; ++ri) {
        const int row = q0 + wid * 16 + ri * 8 + (lane >> 2);
        const float inv = 1.f / l_run[ri];
#pragma unroll
        for (int nt = 0; nt < 8; ++nt) {
            const int col = nt * 8 + (lane & 3) * 2;
            *(__half2*)(o + (tb + row) * EMB + hh * HD + col) =
                __floats2half2_rn(Oa[nt][ri * 2 + 0] * inv,
                                  Oa[nt][ri * 2 + 1] * inv);
        }
    }
}

// ---------------- LayerNorm: fp32 in -> fp16 out ----------------
__global__ void ln_kernel(const float* __restrict__ in, __half* __restrict__ out,
                          const float* __restrict__ gam, const float* __restrict__ bet)
{
    __shared__ float red[8], red2[8];
    __shared__ float s_mu, s_rstd;
    const int row = blockIdx.x;
    const float* x = in + (size_t)row * EMB;
    __half* y = out + (size_t)row * EMB;
    const int tid = threadIdx.x;

    float4 v = *(const float4*)(x + tid * 4);
    float s  = v.x + v.y + v.z + v.w;
    float sq = v.x * v.x + v.y * v.y + v.z * v.z + v.w * v.w;
    const unsigned FULL = 0xffffffffu;
#pragma unroll
    for (int o = 16; o > 0; o >>= 1) {
        s  += __shfl_down_sync(FULL, s, o);
        sq += __shfl_down_sync(FULL, sq, o);
    }
    int warp = tid >> 5, lane = tid & 31;
    if (lane == 0) { red[warp] = s; red2[warp] = sq; }
    __syncthreads();
    if (warp == 0) {
        s  = (lane < 8) ? red[lane]  : 0.f;
        sq = (lane < 8) ? red2[lane] : 0.f;
#pragma unroll
        for (int o = 4; o > 0; o >>= 1) {
            s  += __shfl_down_sync(FULL, s, o);
            sq += __shfl_down_sync(FULL, sq, o);
        }
        if (lane == 0) {
            float mu = s * (1.f / EMB);
            float var = sq * (1.f / EMB) - mu * mu;
            s_mu = mu; s_rstd = rsqrtf(var + LN_EPS);
        }
    }
    __syncthreads();
    const float mu = s_mu, rstd = s_rstd;
    const float4 g4 = *(const float4*)(gam + tid * 4);
    const float4 b4 = *(const float4*)(bet + tid * 4);
    __half2 h0 = __floats2half2_rn((v.x - mu) * rstd * g4.x + b4.x,
                                   (v.y - mu) * rstd * g4.y + b4.y);
    __half2 h1 = __floats2half2_rn((v.z - mu) * rstd * g4.z + b4.z,
                                   (v.w - mu) * rstd * g4.w + b4.w);
    uint2 pk; pk.x = h2u(h0); pk.y = h2u(h1);
    *(uint2*)(y + tid * 4) = pk;
}

// ---------------- launch ----------------
extern "C" void kernel_launch(void* const* d_in, const int* in_sizes, int n_in,
                              void* d_out, int out_size)
{
    const float* x      = (const float*)d_in[0];
    const float* ln1_g  = (const float*)d_in[1];
    const float* ln1_b  = (const float*)d_in[2];
    const float* ln2_g  = (const float*)d_in[3];
    const float* ln2_b  = (const float*)d_in[4];
    const float* w_qkv  = (const float*)d_in[5];
    const float* b_qkv  = (const float*)d_in[6];
    const float* w_proj = (const float*)d_in[7];
    const float* b_proj = (const float*)d_in[8];
    const float* w_fc1  = (const float*)d_in[9];
    const float* b_fc1  = (const float*)d_in[10];
    const float* w_fc2  = (const float*)d_in[11];
    const float* b_fc2  = (const float*)d_in[12];
    float* out = (float*)d_out;

    void *p_h16, *p_qkv16, *p_o16, *p_act16, *p_x1;
    void *p_wq, *p_wp, *p_w1, *p_w2;
    cudaGetSymbolAddress(&p_h16, g_h16);
    cudaGetSymbolAddress(&p_qkv16, g_qkv16);
    cudaGetSymbolAddress(&p_o16, g_o16);
    cudaGetSymbolAddress(&p_act16, g_act16);
    cudaGetSymbolAddress(&p_x1, g_x1);
    cudaGetSymbolAddress(&p_wq, g_wq16);
    cudaGetSymbolAddress(&p_wp, g_wp16);
    cudaGetSymbolAddress(&p_w1, g_w116);
    cudaGetSymbolAddress(&p_w2, g_w216);
    __half* h16   = (__half*)p_h16;
    __half* qkv16 = (__half*)p_qkv16;
    __half* o16   = (__half*)p_o16;
    __half* act16 = (__half*)p_act16;
    float*  x1    = (float*)p_x1;
    __half* wq16  = (__half*)p_wq;
    __half* wp16  = (__half*)p_wp;
    __half* w116  = (__half*)p_w1;
    __half* w216  = (__half*)p_w2;

    cudaFuncSetAttribute(hgemm<0>, cudaFuncAttributeMaxDynamicSharedMemorySize, GEMM_SMEM);
    cudaFuncSetAttribute(hgemm<1>, cudaFuncAttributeMaxDynamicSharedMemorySize, GEMM_SMEM);
    cudaFuncSetAttribute(hgemm<2>, cudaFuncAttributeMaxDynamicSharedMemorySize, GEMM_SMEM);
    cudaFuncSetAttribute(attn_mma, cudaFuncAttributeMaxDynamicSharedMemorySize, ATT_SMEM);

    // 0. weight conversion (fp32 -> fp16), one launch
    f2h_all<<<6144, 256>>>(w_qkv, wq16, w_proj, wp16, w_fc1, w116, w_fc2, w216);

    // 1. LN1 -> h16
    ln_kernel<<<TOK, 256>>>(x, h16, ln1_g, ln1_b);
    // 2. QKV (fp16 out)
    hgemm<0><<<dim3(3 * EMB / 128, TOK / 128), 256, GEMM_SMEM>>>(
        h16, wq16, b_qkv, nullptr, qkv16, TOK, 3 * EMB, EMB);
    // 3. attention (fp16 in/out)
    attn_mma<<<dim3(2 * NH, SEQ / 128), 256, ATT_SMEM>>>(qkv16, o16);
    // 4. proj + residual (fp32 out)
    hgemm<2><<<dim3(EMB / 128, TOK / 128), 256, GEMM_SMEM>>>(
        o16, wp16, b_proj, x, x1, TOK, EMB, EMB);
    // 5. LN2 -> h16
    ln_kernel<<<TOK, 256>>>(x1, h16, ln2_g, ln2_b);
    // 6. FC1 + GELU (fp16 out)
    hgemm<1><<<dim3(MLP / 128, TOK / 128), 256, GEMM_SMEM>>>(
        h16, w116, b_fc1, nullptr, act16, TOK, MLP, EMB);
    // 7. FC2 + residual (fp32 out)
    hgemm<2><<<dim3(EMB / 128, TOK / 128), 256, GEMM_SMEM>>>(
        act16, w216, b_fc2, x1, out, TOK, EMB, MLP);
}

// round 12
// speedup vs baseline: 1.0540x; 1.0185x over previous
#include <cuda_runtime.h>
#include <cuda_fp16.h>
#include <math.h>
#include <stdint.h>

// ---------------- problem constants ----------------
#define TOK   4096
#define EMB   1024
#define NH    16
#define HD    64
#define SEQ   2048
#define MLP   4096
#define LN_EPS 1e-5f
#define SM_SCL 0.18033688011112042f   // 0.125 * log2(e), applied in fp32

// ---------------- scratch ----------------
static __device__ __half g_h16 [(size_t)TOK * EMB];
static __device__ __half g_qkv16[(size_t)TOK * 3 * EMB];
static __device__ __half g_o16 [(size_t)TOK * EMB];
static __device__ __half g_act16[(size_t)TOK * MLP];
static __device__ float  g_x1  [(size_t)TOK * EMB];
static __device__ __half g_wq16[(size_t)EMB * 3 * EMB];
static __device__ __half g_wp16[(size_t)EMB * EMB];
static __device__ __half g_w116[(size_t)EMB * MLP];
static __device__ __half g_w216[(size_t)MLP * EMB];

// ---------------- helpers ----------------
__device__ __forceinline__ uint32_t smem_u32(const void* p) {
    uint32_t a;
    asm("{ .reg .u64 t; cvta.to.shared.u64 t, %1; cvt.u32.u64 %0, t; }" : "=r"(a) : "l"(p));
    return a;
}
__device__ __forceinline__ void sts128(uint32_t addr, uint4 v) {
    asm volatile("st.shared.v4.b32 [%0], {%1, %2, %3, %4};"
        :: "r"(addr), "r"(v.x), "r"(v.y), "r"(v.z), "r"(v.w));
}
__device__ __forceinline__ uint32_t h2u(__half2 h) { return *(uint32_t*)&h; }
// 64B rows: 16B chunk bits [4:6) ^= (row>>1)&3
__device__ __forceinline__ uint32_t swz(uint32_t off) {
    return off ^ (((off >> 7) & 3u) << 4);
}
// 128B rows: 16B chunk bits [4:7) ^= row&7
__device__ __forceinline__ uint32_t sw128(uint32_t off) {
    return off ^ ((off >> 3) & 0x70u);
}
// 256B rows: 16B chunk bits [4:7) ^= row&7
__device__ __forceinline__ uint32_t sw256(uint32_t off) {
    return off ^ (((off >> 8) & 7u) << 4);
}
__device__ __forceinline__ void ldsm_x4(uint32_t addr, uint32_t* r) {
    asm volatile("ldmatrix.sync.aligned.m8n8.x4.shared.b16 {%0,%1,%2,%3}, [%4];"
        : "=r"(r[0]), "=r"(r[1]), "=r"(r[2]), "=r"(r[3]) : "r"(addr));
}
__device__ __forceinline__ void ldsm_x4_t(uint32_t addr, uint32_t* r) {
    asm volatile("ldmatrix.sync.aligned.m8n8.x4.trans.shared.b16 {%0,%1,%2,%3}, [%4];"
        : "=r"(r[0]), "=r"(r[1]), "=r"(r[2]), "=r"(r[3]) : "r"(addr));
}
__device__ __forceinline__ void mma16816(float* d, const uint32_t* a, const uint32_t* b) {
    asm volatile("mma.sync.aligned.m16n8k16.row.col.f32.f16.f16.f32 "
        "{%0,%1,%2,%3}, {%4,%5,%6,%7}, {%8,%9}, {%0,%1,%2,%3};"
        : "+f"(d[0]), "+f"(d[1]), "+f"(d[2]), "+f"(d[3])
        : "r"(a[0]), "r"(a[1]), "r"(a[2]), "r"(a[3]), "r"(b[0]), "r"(b[1]));
}
__device__ __forceinline__ void cpasync16(uint32_t saddr, const void* g) {
    asm volatile("cp.async.cg.shared.global [%0], [%1], 16;" :: "r"(saddr), "l"(g));
}
#define CP_COMMIT() asm volatile("cp.async.commit_group;" ::: "memory")
#define CP_WAIT2()  asm volatile("cp.async.wait_group 2;" ::: "memory")
#define CP_WAIT1()  asm volatile("cp.async.wait_group 1;" ::: "memory")
__device__ __forceinline__ float gelu_exact(float x) {
    return 0.5f * x * (1.f + erff(x * 0.70710678118654752f));
}

// ---------------- LayerNorm row body (shared by 2 kernels) ----------------
__device__ __forceinline__ void ln_row(const float* __restrict__ x, __half* __restrict__ y,
                                       const float* __restrict__ gam,
                                       const float* __restrict__ bet, int tid)
{
    __shared__ float red[8], red2[8];
    __shared__ float s_mu, s_rstd;
    float4 v = *(const float4*)(x + tid * 4);
    float s  = v.x + v.y + v.z + v.w;
    float sq = v.x * v.x + v.y * v.y + v.z * v.z + v.w * v.w;
    const unsigned FULL = 0xffffffffu;
#pragma unroll
    for (int o = 16; o > 0; o >>= 1) {
        s  += __shfl_down_sync(FULL, s, o);
        sq += __shfl_down_sync(FULL, sq, o);
    }
    int warp = tid >> 5, lane = tid & 31;
    if (lane == 0) { red[warp] = s; red2[warp] = sq; }
    __syncthreads();
    if (warp == 0) {
        s  = (lane < 8) ? red[lane]  : 0.f;
        sq = (lane < 8) ? red2[lane] : 0.f;
#pragma unroll
        for (int o = 4; o > 0; o >>= 1) {
            s  += __shfl_down_sync(FULL, s, o);
            sq += __shfl_down_sync(FULL, sq, o);
        }
        if (lane == 0) {
            float mu = s * (1.f / EMB);
            float var = sq * (1.f / EMB) - mu * mu;
            s_mu = mu; s_rstd = rsqrtf(var + LN_EPS);
        }
    }
    __syncthreads();
    const float mu = s_mu, rstd = s_rstd;
    const float4 g4 = *(const float4*)(gam + tid * 4);
    const float4 b4 = *(const float4*)(bet + tid * 4);
    __half2 h0 = __floats2half2_rn((v.x - mu) * rstd * g4.x + b4.x,
                                   (v.y - mu) * rstd * g4.y + b4.y);
    __half2 h1 = __floats2half2_rn((v.z - mu) * rstd * g4.z + b4.z,
                                   (v.w - mu) * rstd * g4.w + b4.w);
    uint2 pk; pk.x = h2u(h0); pk.y = h2u(h1);
    *(uint2*)(y + tid * 4) = pk;
}

// =====================================================================
// prep: f2h of all 4 weights (blocks 0..6143) + LN1 (blocks 6144..10239)
// =====================================================================
__global__ void prep_kernel(const float* __restrict__ wq, __half* __restrict__ dq,
                            const float* __restrict__ wp, __half* __restrict__ dp,
                            const float* __restrict__ w1, __half* __restrict__ d1,
                            const float* __restrict__ w2, __half* __restrict__ d2,
                            const float* __restrict__ x,  __half* __restrict__ h16,
                            const float* __restrict__ g,  const float* __restrict__ bb)
{
    const int b = blockIdx.x;
    if (b >= 6144) {
        const int row = b - 6144;
        ln_row(x + (size_t)row * EMB, h16 + (size_t)row * EMB, g, bb, threadIdx.x);
        return;
    }
    const float* src; __half* dst; int rb;
    if (b < 1536)      { src = wq; dst = dq; rb = b; }
    else if (b < 2048) { src = wp; dst = dp; rb = b - 1536; }
    else if (b < 4096) { src = w1; dst = d1; rb = b - 2048; }
    else               { src = w2; dst = d2; rb = b - 4096; }
    const int i = (rb * 256 + threadIdx.x) * 8;
    float4 a = *(const float4*)(src + i);
    float4 c = *(const float4*)(src + i + 4);
    uint4 o;
    o.x = h2u(__floats2half2_rn(a.x, a.y));
    o.y = h2u(__floats2half2_rn(a.z, a.w));
    o.z = h2u(__floats2half2_rn(c.x, c.y));
    o.w = h2u(__floats2half2_rn(c.z, c.w));
    *(uint4*)(dst + i) = o;
}

__global__ void ln_kernel(const float* __restrict__ in, __half* __restrict__ out,
                          const float* __restrict__ gam, const float* __restrict__ bet)
{
    ln_row(in + (size_t)blockIdx.x * EMB, out + (size_t)blockIdx.x * EMB, gam, bet, threadIdx.x);
}

// =====================================================================
// HMMA GEMM, all-fp16 operands, cp.async 4-stage pipeline. (unchanged)
// MODE: 0 = bias -> fp16, 1 = bias+gelu -> fp16, 2 = bias+res -> fp32
// =====================================================================
#define GEMM_SMEM (4 * 16384)

template<int MODE>
__global__ void __launch_bounds__(256, 2)
hgemm(const __half* __restrict__ A, const __half* __restrict__ B,
      const float* __restrict__ bias, const float* __restrict__ res,
      void* __restrict__ Cout, int M, int N, int K)
{
    extern __shared__ char dsm[];
    const uint32_t base = smem_u32(dsm);

    const int tid  = threadIdx.x;
    const int lane = tid & 31, wid = tid >> 5;
    const int wm = (wid & 1) * 64;
    const int wn = (wid >> 1) * 32;
    const int bm = blockIdx.y * 128, bn = blockIdx.x * 128;
    const int g = lane >> 3;

    float acc[4][4][4];
#pragma unroll
    for (int i = 0; i < 4; ++i)
#pragma unroll
        for (int j = 0; j < 4; ++j)
#pragma unroll
            for (int c = 0; c < 4; ++c) acc[i][j][c] = 0.f;

    const int nch = K / 32;

    auto issue = [&](int buf, int kc) {
        const uint32_t sA = base + buf * 16384u;
        const uint32_t sB = sA + 8192u;
#pragma unroll
        for (int i = 0; i < 2; ++i) {
            const int cc = tid * 2 + i;
            const int rowa = cc >> 2, kch = cc & 3;
            cpasync16(sA + swz((uint32_t)(rowa * 64 + kch * 16)),
                      A + (size_t)(bm + rowa) * K + kc * 32 + kch * 8);
            const int rowb = cc >> 4, nch2 = cc & 15;
            cpasync16(sB + sw256((uint32_t)(rowb * 256 + nch2 * 16)),
                      B + (size_t)(kc * 32 + rowb) * N + bn + nch2 * 8);
        }
    };

    auto compute = [&](int buf) {
        const uint32_t sA = base + buf * 16384u;
        const uint32_t sB = sA + 8192u;
#pragma unroll
        for (int ks = 0; ks < 2; ++ks) {
            uint32_t AF[4][4];
            const int ra = wm + (g & 1) * 8 + (lane & 7);
            const int ca = ks * 32 + (g >> 1) * 16;
#pragma unroll
            for (int mt = 0; mt < 4; ++mt)
                ldsm_x4(sA + swz((uint32_t)((ra + mt * 16) * 64 + ca)), AF[mt]);
            const int rb = ks * 16 + (g & 1) * 8 + (lane & 7);
#pragma unroll
            for (int p = 0; p < 2; ++p) {
                uint32_t t[4];
                const int cbb = (wn + p * 16) * 2 + (g >> 1) * 16;
                ldsm_x4_t(sB + sw256((uint32_t)(rb * 256 + cbb)), t);
#pragma unroll
                for (int mt = 0; mt < 4; ++mt) {
                    mma16816(acc[mt][p * 2 + 0], AF[mt], t);
                    mma16816(acc[mt][p * 2 + 1], AF[mt], t + 2);
                }
            }
        }
    };

    issue(0, 0); CP_COMMIT();
    issue(1, 1); CP_COMMIT();
    issue(2, 2); CP_COMMIT();

    for (int kc = 0; kc < nch; ++kc) {
        CP_WAIT2();
        __syncthreads();
        compute(kc & 3);
        if (kc + 3 < nch) issue((kc + 3) & 3, kc + 3);
        CP_COMMIT();
    }

#pragma unroll
    for (int mt = 0; mt < 4; ++mt) {
#pragma unroll
        for (int nt = 0; nt < 4; ++nt) {
            const int col = bn + wn + nt * 8 + (lane & 3) * 2;
            const float b0 = bias[col], b1 = bias[col + 1];
#pragma unroll
            for (int dp = 0; dp < 2; ++dp) {
                const int row = bm + wm + mt * 16 + (lane >> 2) + dp * 8;
                float o0 = acc[mt][nt][dp * 2 + 0] + b0;
                float o1 = acc[mt][nt][dp * 2 + 1] + b1;
                if (MODE == 1) { o0 = gelu_exact(o0); o1 = gelu_exact(o1); }
                if (MODE == 2) {
                    const float2 rv = *(const float2*)(res + (size_t)row * N + col);
                    float2 ov; ov.x = o0 + rv.x; ov.y = o1 + rv.y;
                    *(float2*)((float*)Cout + (size_t)row * N + col) = ov;
                } else {
                    *(__half2*)((__half*)Cout + (size_t)row * N + col) =
                        __floats2half2_rn(o0, o1);
                }
            }
        }
    }
}

// =====================================================================
// HMMA flash attention v3: warp-owns-rows, base-2 softmax with f16x2 exp,
// row-sum l via ones-fragment MMA (exact fp32, no shuffles).
// CTA = (b, head) x 128 queries, 256 threads; key tile 64, cp.async x2.
// =====================================================================
#define ATT_SMEM (16384 + 2 * 16384)

__global__ void __launch_bounds__(256, 2)
attn_mma(const __half* __restrict__ qkv, __half* __restrict__ o)
{
    extern __shared__ char dynsm[];
    const uint32_t Qb = smem_u32(dynsm);

    const int tid  = threadIdx.x;
    const int lane = tid & 31, wid = tid >> 5;
    const int b = blockIdx.x >> 4, hh = blockIdx.x & 15;
    const int q0 = blockIdx.y * 128;
    const size_t tb = (size_t)b * SEQ;
    const size_t RS = 3 * EMB;
    const unsigned FULL = 0xffffffffu;
    const int g = lane >> 3;
    const uint32_t ONES[2] = {0x3C003C00u, 0x3C003C00u};

    auto issueKV = [&](int s, int kt) {
        const uint32_t Kb = Qb + 16384u + (uint32_t)s * 16384u;
        const uint32_t Vb = Kb + 8192u;
        const __half* kbase = qkv + (tb + kt * 64) * RS + EMB + hh * HD;
#pragma unroll
        for (int i = 0; i < 2; ++i) {
            const int cc = tid * 2 + i;
            const int r = cc >> 3, ch = cc & 7;
            const uint32_t off = sw128((uint32_t)(r * 128 + ch * 16));
            cpasync16(Kb + off, kbase + (size_t)r * RS + ch * 8);
            cpasync16(Vb + off, kbase + EMB + (size_t)r * RS + ch * 8);
        }
    };

    // ---- load Q tile (raw fp16; scale folded into softmax) ----
    {
        const int r = tid >> 1, c0 = (tid & 1) * 32;
        const __half* qp = qkv + (tb + q0 + r) * RS + hh * HD + c0;
#pragma unroll
        for (int j = 0; j < 4; ++j)
            sts128(Qb + sw128((uint32_t)(r * 128 + (c0 + j * 8) * 2)),
                   *(const uint4*)(qp + j * 8));
    }
    issueKV(0, 0); CP_COMMIT();
    __syncthreads();

    uint32_t QF[4][4];
#pragma unroll
    for (int t = 0; t < 4; ++t) {
        const int r = wid * 16 + (g & 1) * 8 + (lane & 7);
        const int cb = t * 32 + (g >> 1) * 16;
        ldsm_x4(Qb + sw128((uint32_t)(r * 128 + cb)), QF[t]);
    }

    float Oa[8][4];
#pragma unroll
    for (int nt = 0; nt < 8; ++nt)
#pragma unroll
        for (int c = 0; c < 4; ++c) Oa[nt][c] = 0.f;
    float lacc[4] = {0.f, 0.f, 0.f, 0.f};           // MMA row-sum accumulator
    float m_run[2] = {-INFINITY, -INFINITY};        // raw-score running max

    for (int kt = 0; kt < SEQ / 64; ++kt) {
        __syncthreads();
        if (kt + 1 < SEQ / 64) issueKV((kt + 1) & 1, kt + 1);
        CP_COMMIT();
        CP_WAIT1();
        __syncthreads();

        const uint32_t Kb = Qb + 16384u + (uint32_t)(kt & 1) * 16384u;
        const uint32_t Vb = Kb + 8192u;

        // ---- S = Q K^T (raw scores) ----
        float sacc[8][4];
#pragma unroll
        for (int nt = 0; nt < 8; ++nt)
#pragma unroll
            for (int c = 0; c < 4; ++c) sacc[nt][c] = 0.f;

#pragma unroll
        for (int t = 0; t < 4; ++t) {
#pragma unroll
            for (int pr = 0; pr < 4; ++pr) {
                const int r = pr * 16 + (g >> 1) * 8 + (lane & 7);
                const int cb = t * 32 + (g & 1) * 16;
                uint32_t tt[4];
                ldsm_x4(Kb + sw128((uint32_t)(r * 128 + cb)), tt);
                mma16816(sacc[pr * 2 + 0], QF[t], tt);
                mma16816(sacc[pr * 2 + 1], QF[t], tt + 2);
            }
        }

        // ---- online softmax: max on raw scores, base-2 exp in f16x2 ----
        float fexp[2];
#pragma unroll
        for (int ri = 0; ri < 2; ++ri) {
            float mx = sacc[0][ri * 2];
#pragma unroll
            for (int nt = 0; nt < 8; ++nt) {
                mx = fmaxf(mx, sacc[nt][ri * 2]);
                mx = fmaxf(mx, sacc[nt][ri * 2 + 1]);
            }
            mx = fmaxf(mx, __shfl_xor_sync(FULL, mx, 1));
            mx = fmaxf(mx, __shfl_xor_sync(FULL, mx, 2));
            const float mn = fmaxf(m_run[ri], mx);
            fexp[ri] = exp2f((m_run[ri] - mn) * SM_SCL);
            m_run[ri] = mn;
        }
        const float negm0 = -m_run[0] * SM_SCL;
        const float negm1 = -m_run[1] * SM_SCL;

        uint32_t P0[8], P1[8];
#pragma unroll
        for (int nt = 0; nt < 8; ++nt) {
            __half2 d0 = __floats2half2_rn(fmaf(sacc[nt][0], SM_SCL, negm0),
                                           fmaf(sacc[nt][1], SM_SCL, negm0));
            __half2 d1 = __floats2half2_rn(fmaf(sacc[nt][2], SM_SCL, negm1),
                                           fmaf(sacc[nt][3], SM_SCL, negm1));
            P0[nt] = h2u(h2exp2(d0));
            P1[nt] = h2u(h2exp2(d1));
        }

        // ---- rescale O and l ----
#pragma unroll
        for (int nt = 0; nt < 8; ++nt)
#pragma unroll
            for (int c = 0; c < 4; ++c)
                Oa[nt][c] *= fexp[c >> 1];
        lacc[0] *= fexp[0]; lacc[1] *= fexp[0];
        lacc[2] *= fexp[1]; lacc[3] *= fexp[1];

        // ---- O += P V ; l += P @ 1 ----
#pragma unroll
        for (int k2 = 0; k2 < 4; ++k2) {
            uint32_t pa[4];
            pa[0] = P0[2 * k2];     pa[1] = P1[2 * k2];
            pa[2] = P0[2 * k2 + 1]; pa[3] = P1[2 * k2 + 1];
            mma16816(lacc, pa, ONES);                 // row sums, exact fp32
#pragma unroll
            for (int npr = 0; npr < 4; ++npr) {
                const int r = k2 * 16 + (g & 1) * 8 + (lane & 7);
                const int cb = npr * 32 + (g >> 1) * 16;
                uint32_t tt[4];
                ldsm_x4_t(Vb + sw128((uint32_t)(r * 128 + cb)), tt);
                mma16816(Oa[npr * 2 + 0], pa, tt);
                mma16816(Oa[npr * 2 + 1], pa, tt + 2);
            }
        }
    }

    // ---- finalize: every lane holds full row sum in lacc[2*ri] ----
#pragma unroll
    for (int ri = 0; ri < 2; ++ri) {
        const int row = q0 + wid * 16 + ri * 8 + (lane >> 2);
        const float inv = 1.f / lacc[ri * 2];
#pragma unroll
        for (int nt = 0; nt < 8; ++nt) {
            const int col = nt * 8 + (lane & 3) * 2;
            *(__half2*)(o + (tb + row) * EMB + hh * HD + col) =
                __floats2half2_rn(Oa[nt][ri * 2 + 0] * inv,
                                  Oa[nt][ri * 2 + 1] * inv);
        }
    }
}

// ---------------- launch ----------------
extern "C" void kernel_launch(void* const* d_in, const int* in_sizes, int n_in,
                              void* d_out, int out_size)
{
    const float* x      = (const float*)d_in[0];
    const float* ln1_g  = (const float*)d_in[1];
    const float* ln1_b  = (const float*)d_in[2];
    const float* ln2_g  = (const float*)d_in[3];
    const float* ln2_b  = (const float*)d_in[4];
    const float* w_qkv  = (const float*)d_in[5];
    const float* b_qkv  = (const float*)d_in[6];
    const float* w_proj = (const float*)d_in[7];
    const float* b_proj = (const float*)d_in[8];
    const float* w_fc1  = (const float*)d_in[9];
    const float* b_fc1  = (const float*)d_in[10];
    const float* w_fc2  = (const float*)d_in[11];
    const float* b_fc2  = (const float*)d_in[12];
    float* out = (float*)d_out;

    void *p_h16, *p_qkv16, *p_o16, *p_act16, *p_x1;
    void *p_wq, *p_wp, *p_w1, *p_w2;
    cudaGetSymbolAddress(&p_h16, g_h16);
    cudaGetSymbolAddress(&p_qkv16, g_qkv16);
    cudaGetSymbolAddress(&p_o16, g_o16);
    cudaGetSymbolAddress(&p_act16, g_act16);
    cudaGetSymbolAddress(&p_x1, g_x1);
    cudaGetSymbolAddress(&p_wq, g_wq16);
    cudaGetSymbolAddress(&p_wp, g_wp16);
    cudaGetSymbolAddress(&p_w1, g_w116);
    cudaGetSymbolAddress(&p_w2, g_w216);
    __half* h16   = (__half*)p_h16;
    __half* qkv16 = (__half*)p_qkv16;
    __half* o16   = (__half*)p_o16;
    __half* act16 = (__half*)p_act16;
    float*  x1    = (float*)p_x1;
    __half* wq16  = (__half*)p_wq;
    __half* wp16  = (__half*)p_wp;
    __half* w116  = (__half*)p_w1;
    __half* w216  = (__half*)p_w2;

    cudaFuncSetAttribute(hgemm<0>, cudaFuncAttributeMaxDynamicSharedMemorySize, GEMM_SMEM);
    cudaFuncSetAttribute(hgemm<1>, cudaFuncAttributeMaxDynamicSharedMemorySize, GEMM_SMEM);
    cudaFuncSetAttribute(hgemm<2>, cudaFuncAttributeMaxDynamicSharedMemorySize, GEMM_SMEM);
    cudaFuncSetAttribute(attn_mma, cudaFuncAttributeMaxDynamicSharedMemorySize, ATT_SMEM);

    // 0. weight f2h + LN1 in one launch
    prep_kernel<<<6144 + TOK, 256>>>(w_qkv, wq16, w_proj, wp16, w_fc1, w116,
                                     w_fc2, w216, x, h16, ln1_g, ln1_b);
    // 1. QKV (fp16 out)
    hgemm<0><<<dim3(3 * EMB / 128, TOK / 128), 256, GEMM_SMEM>>>(
        h16, wq16, b_qkv, nullptr, qkv16, TOK, 3 * EMB, EMB);
    // 2. attention (fp16 in/out)
    attn_mma<<<dim3(2 * NH, SEQ / 128), 256, ATT_SMEM>>>(qkv16, o16);
    // 3. proj + residual (fp32 out)
    hgemm<2><<<dim3(EMB / 128, TOK / 128), 256, GEMM_SMEM>>>(
        o16, wp16, b_proj, x, x1, TOK, EMB, EMB);
    // 4. LN2 -> h16
    ln_kernel<<<TOK, 256>>>(x1, h16, ln2_g, ln2_b);
    // 5. FC1 + GELU (fp16 out)
    hgemm<1><<<dim3(MLP / 128, TOK / 128), 256, GEMM_SMEM>>>(
        h16, w116, b_fc1, nullptr, act16, TOK, MLP, EMB);
    // 6. FC2 + residual (fp32 out)
    hgemm<2><<<dim3(EMB / 128, TOK / 128), 256, GEMM_SMEM>>>(
        act16, w216, b_fc2, x1, out, TOK, EMB, MLP);
}

// round 13
// speedup vs baseline: 1.1310x; 1.0730x over previous
#include <cuda_runtime.h>
#include <cuda_fp16.h>
#include <math.h>
#include <stdint.h>

// ---------------- problem constants ----------------
#define TOK   4096
#define EMB   1024
#define NH    16
#define HD    64
#define SEQ   2048
#define MLP   4096
#define LN_EPS 1e-5f
#define SM_SCL 0.18033688011112042f   // 0.125 * log2(e)

// ---------------- scratch ----------------
static __device__ __half g_h16 [(size_t)TOK * EMB];
static __device__ __half g_qkv16[(size_t)TOK * 3 * EMB];
static __device__ __half g_o16 [(size_t)TOK * EMB];
static __device__ __half g_act16[(size_t)TOK * MLP];
static __device__ float  g_x1  [(size_t)TOK * EMB];
static __device__ __half g_wq16[(size_t)EMB * 3 * EMB];
static __device__ __half g_wp16[(size_t)EMB * EMB];
static __device__ __half g_w116[(size_t)EMB * MLP];
static __device__ __half g_w216[(size_t)MLP * EMB];

// ---------------- helpers ----------------
__device__ __forceinline__ uint32_t smem_u32(const void* p) {
    uint32_t a;
    asm("{ .reg .u64 t; cvta.to.shared.u64 t, %1; cvt.u32.u64 %0, t; }" : "=r"(a) : "l"(p));
    return a;
}
__device__ __forceinline__ void sts128(uint32_t addr, uint4 v) {
    asm volatile("st.shared.v4.b32 [%0], {%1, %2, %3, %4};"
        :: "r"(addr), "r"(v.x), "r"(v.y), "r"(v.z), "r"(v.w));
}
__device__ __forceinline__ uint32_t h2u(__half2 h) { return *(uint32_t*)&h; }
// 128B rows: 16B chunk bits [4:7) ^= row&7
__device__ __forceinline__ uint32_t sw128(uint32_t off) {
    return off ^ ((off >> 3) & 0x70u);
}
// 256B rows
__device__ __forceinline__ uint32_t sw256(uint32_t off) {
    return off ^ (((off >> 8) & 7u) << 4);
}
__device__ __forceinline__ void ldsm_x4(uint32_t addr, uint32_t* r) {
    asm volatile("ldmatrix.sync.aligned.m8n8.x4.shared.b16 {%0,%1,%2,%3}, [%4];"
        : "=r"(r[0]), "=r"(r[1]), "=r"(r[2]), "=r"(r[3]) : "r"(addr));
}
__device__ __forceinline__ void ldsm_x4_t(uint32_t addr, uint32_t* r) {
    asm volatile("ldmatrix.sync.aligned.m8n8.x4.trans.shared.b16 {%0,%1,%2,%3}, [%4];"
        : "=r"(r[0]), "=r"(r[1]), "=r"(r[2]), "=r"(r[3]) : "r"(addr));
}
__device__ __forceinline__ void mma16816(float* d, const uint32_t* a, const uint32_t* b) {
    asm volatile("mma.sync.aligned.m16n8k16.row.col.f32.f16.f16.f32 "
        "{%0,%1,%2,%3}, {%4,%5,%6,%7}, {%8,%9}, {%0,%1,%2,%3};"
        : "+f"(d[0]), "+f"(d[1]), "+f"(d[2]), "+f"(d[3])
        : "r"(a[0]), "r"(a[1]), "r"(a[2]), "r"(a[3]), "r"(b[0]), "r"(b[1]));
}
__device__ __forceinline__ void cpasync16(uint32_t saddr, const void* g) {
    asm volatile("cp.async.cg.shared.global [%0], [%1], 16;" :: "r"(saddr), "l"(g));
}
#define CP_COMMIT() asm volatile("cp.async.commit_group;" ::: "memory")
#define CP_WAIT1()  asm volatile("cp.async.wait_group 1;" ::: "memory")
__device__ __forceinline__ float gelu_exact(float x) {
    return 0.5f * x * (1.f + erff(x * 0.70710678118654752f));
}

// ---------------- LayerNorm row body ----------------
__device__ __forceinline__ void ln_row(const float* __restrict__ x, __half* __restrict__ y,
                                       const float* __restrict__ gam,
                                       const float* __restrict__ bet, int tid)
{
    __shared__ float red[8], red2[8];
    __shared__ float s_mu, s_rstd;
    float4 v = *(const float4*)(x + tid * 4);
    float s  = v.x + v.y + v.z + v.w;
    float sq = v.x * v.x + v.y * v.y + v.z * v.z + v.w * v.w;
    const unsigned FULL = 0xffffffffu;
#pragma unroll
    for (int o = 16; o > 0; o >>= 1) {
        s  += __shfl_down_sync(FULL, s, o);
        sq += __shfl_down_sync(FULL, sq, o);
    }
    int warp = tid >> 5, lane = tid & 31;
    if (lane == 0) { red[warp] = s; red2[warp] = sq; }
    __syncthreads();
    if (warp == 0) {
        s  = (lane < 8) ? red[lane]  : 0.f;
        sq = (lane < 8) ? red2[lane] : 0.f;
#pragma unroll
        for (int o = 4; o > 0; o >>= 1) {
            s  += __shfl_down_sync(FULL, s, o);
            sq += __shfl_down_sync(FULL, sq, o);
        }
        if (lane == 0) {
            float mu = s * (1.f / EMB);
            float var = sq * (1.f / EMB) - mu * mu;
            s_mu = mu; s_rstd = rsqrtf(var + LN_EPS);
        }
    }
    __syncthreads();
    const float mu = s_mu, rstd = s_rstd;
    const float4 g4 = *(const float4*)(gam + tid * 4);
    const float4 b4 = *(const float4*)(bet + tid * 4);
    __half2 h0 = __floats2half2_rn((v.x - mu) * rstd * g4.x + b4.x,
                                   (v.y - mu) * rstd * g4.y + b4.y);
    __half2 h1 = __floats2half2_rn((v.z - mu) * rstd * g4.z + b4.z,
                                   (v.w - mu) * rstd * g4.w + b4.w);
    uint2 pk; pk.x = h2u(h0); pk.y = h2u(h1);
    *(uint2*)(y + tid * 4) = pk;
}

// =====================================================================
// prep: f2h of all 4 weights (blocks 0..6143) + LN1 (blocks 6144..10239)
// =====================================================================
__global__ void prep_kernel(const float* __restrict__ wq, __half* __restrict__ dq,
                            const float* __restrict__ wp, __half* __restrict__ dp,
                            const float* __restrict__ w1, __half* __restrict__ d1,
                            const float* __restrict__ w2, __half* __restrict__ d2,
                            const float* __restrict__ x,  __half* __restrict__ h16,
                            const float* __restrict__ g,  const float* __restrict__ bb)
{
    const int b = blockIdx.x;
    if (b >= 6144) {
        const int row = b - 6144;
        ln_row(x + (size_t)row * EMB, h16 + (size_t)row * EMB, g, bb, threadIdx.x);
        return;
    }
    const float* src; __half* dst; int rb;
    if (b < 1536)      { src = wq; dst = dq; rb = b; }
    else if (b < 2048) { src = wp; dst = dp; rb = b - 1536; }
    else if (b < 4096) { src = w1; dst = d1; rb = b - 2048; }
    else               { src = w2; dst = d2; rb = b - 4096; }
    const int i = (rb * 256 + threadIdx.x) * 8;
    float4 a = *(const float4*)(src + i);
    float4 c = *(const float4*)(src + i + 4);
    uint4 o;
    o.x = h2u(__floats2half2_rn(a.x, a.y));
    o.y = h2u(__floats2half2_rn(a.z, a.w));
    o.z = h2u(__floats2half2_rn(c.x, c.y));
    o.w = h2u(__floats2half2_rn(c.z, c.w));
    *(uint4*)(dst + i) = o;
}

__global__ void ln_kernel(const float* __restrict__ in, __half* __restrict__ out,
                          const float* __restrict__ gam, const float* __restrict__ bet)
{
    ln_row(in + (size_t)blockIdx.x * EMB, out + (size_t)blockIdx.x * EMB, gam, bet, threadIdx.x);
}

// =====================================================================
// HMMA GEMM v2: compile-time N/K, BK=64, 3-stage cp.async pipeline.
// Block 128x128, 8 warps (2M x 4N) of 64x32.
// smem/stage: A [128][64]h (128B rows, sw128) 16KB | B [64][128]h (256B rows) 16KB
// MODE: 0 = bias -> fp16, 1 = bias+gelu -> fp16, 2 = bias+res -> fp32
// =====================================================================
#define GEMM_SMEM (3 * 32768)

template<int MODE, int NN, int KK>
__global__ void __launch_bounds__(256, 2)
hgemm(const __half* __restrict__ A, const __half* __restrict__ B,
      const float* __restrict__ bias, const float* __restrict__ res,
      void* __restrict__ Cout)
{
    extern __shared__ char dsm[];
    const uint32_t base = smem_u32(dsm);

    const int tid  = threadIdx.x;
    const int lane = tid & 31, wid = tid >> 5;
    const int wm = (wid & 1) * 64;
    const int wn = (wid >> 1) * 32;
    const int bm = blockIdx.y * 128, bn = blockIdx.x * 128;
    const int g = lane >> 3;

    float acc[4][4][4];
#pragma unroll
    for (int i = 0; i < 4; ++i)
#pragma unroll
        for (int j = 0; j < 4; ++j)
#pragma unroll
            for (int c = 0; c < 4; ++c) acc[i][j][c] = 0.f;

    constexpr int nch = KK / 64;

    auto issue = [&](int buf, int kc) {
        const uint32_t sA = base + buf * 32768u;
        const uint32_t sB = sA + 16384u;
#pragma unroll
        for (int i = 0; i < 4; ++i) {
            const int cc = tid + i * 256;           // 0..1023
            const int rowa = cc >> 3, kch = cc & 7;
            cpasync16(sA + sw128((uint32_t)(rowa * 128 + kch * 16)),
                      A + (size_t)(bm + rowa) * KK + kc * 64 + kch * 8);
            const int rowb = cc >> 4, nch2 = cc & 15;
            cpasync16(sB + sw256((uint32_t)(rowb * 256 + nch2 * 16)),
                      B + (size_t)(kc * 64 + rowb) * NN + bn + nch2 * 8);
        }
    };

    auto compute = [&](int buf) {
        const uint32_t sA = base + buf * 32768u;
        const uint32_t sB = sA + 16384u;
#pragma unroll
        for (int ks = 0; ks < 4; ++ks) {
            uint32_t AF[4][4];
            const int ra = wm + (g & 1) * 8 + (lane & 7);
            const int ca = ks * 32 + (g >> 1) * 16;
#pragma unroll
            for (int mt = 0; mt < 4; ++mt)
                ldsm_x4(sA + sw128((uint32_t)((ra + mt * 16) * 128 + ca)), AF[mt]);
            const int rb = ks * 16 + (g & 1) * 8 + (lane & 7);
#pragma unroll
            for (int p = 0; p < 2; ++p) {
                uint32_t t[4];
                const int cbb = (wn + p * 16) * 2 + (g >> 1) * 16;
                ldsm_x4_t(sB + sw256((uint32_t)(rb * 256 + cbb)), t);
#pragma unroll
                for (int mt = 0; mt < 4; ++mt) {
                    mma16816(acc[mt][p * 2 + 0], AF[mt], t);
                    mma16816(acc[mt][p * 2 + 1], AF[mt], t + 2);
                }
            }
        }
    };

    issue(0, 0); CP_COMMIT();
    issue(1, 1); CP_COMMIT();

    int cur = 0;
    for (int kc = 0; kc < nch; ++kc) {
        CP_WAIT1();
        __syncthreads();
        compute(cur);
        if (kc + 2 < nch) {
            int nxt = cur + 2; if (nxt >= 3) nxt -= 3;
            issue(nxt, kc + 2);
        }
        CP_COMMIT();
        if (++cur == 3) cur = 0;
    }

#pragma unroll
    for (int mt = 0; mt < 4; ++mt) {
#pragma unroll
        for (int nt = 0; nt < 4; ++nt) {
            const int col = bn + wn + nt * 8 + (lane & 3) * 2;
            const float b0 = bias[col], b1 = bias[col + 1];
#pragma unroll
            for (int dp = 0; dp < 2; ++dp) {
                const int row = bm + wm + mt * 16 + (lane >> 2) + dp * 8;
                float o0 = acc[mt][nt][dp * 2 + 0] + b0;
                float o1 = acc[mt][nt][dp * 2 + 1] + b1;
                if (MODE == 1) { o0 = gelu_exact(o0); o1 = gelu_exact(o1); }
                if (MODE == 2) {
                    const float2 rv = *(const float2*)(res + (size_t)row * NN + col);
                    float2 ov; ov.x = o0 + rv.x; ov.y = o1 + rv.y;
                    *(float2*)((float*)Cout + (size_t)row * NN + col) = ov;
                } else {
                    *(__half2*)((__half*)Cout + (size_t)row * NN + col) =
                        __floats2half2_rn(o0, o1);
                }
            }
        }
    }
}

// =====================================================================
// HMMA flash attention v3 (unchanged from R12)
// =====================================================================
#define ATT_SMEM (16384 + 2 * 16384)

__global__ void __launch_bounds__(256, 2)
attn_mma(const __half* __restrict__ qkv, __half* __restrict__ o)
{
    extern __shared__ char dynsm[];
    const uint32_t Qb = smem_u32(dynsm);

    const int tid  = threadIdx.x;
    const int lane = tid & 31, wid = tid >> 5;
    const int b = blockIdx.x >> 4, hh = blockIdx.x & 15;
    const int q0 = blockIdx.y * 128;
    const size_t tb = (size_t)b * SEQ;
    const size_t RS = 3 * EMB;
    const unsigned FULL = 0xffffffffu;
    const int g = lane >> 3;
    const uint32_t ONES[2] = {0x3C003C00u, 0x3C003C00u};

    auto issueKV = [&](int s, int kt) {
        const uint32_t Kb = Qb + 16384u + (uint32_t)s * 16384u;
        const uint32_t Vb = Kb + 8192u;
        const __half* kbase = qkv + (tb + kt * 64) * RS + EMB + hh * HD;
#pragma unroll
        for (int i = 0; i < 2; ++i) {
            const int cc = tid * 2 + i;
            const int r = cc >> 3, ch = cc & 7;
            const uint32_t off = sw128((uint32_t)(r * 128 + ch * 16));
            cpasync16(Kb + off, kbase + (size_t)r * RS + ch * 8);
            cpasync16(Vb + off, kbase + EMB + (size_t)r * RS + ch * 8);
        }
    };

    {
        const int r = tid >> 1, c0 = (tid & 1) * 32;
        const __half* qp = qkv + (tb + q0 + r) * RS + hh * HD + c0;
#pragma unroll
        for (int j = 0; j < 4; ++j)
            sts128(Qb + sw128((uint32_t)(r * 128 + (c0 + j * 8) * 2)),
                   *(const uint4*)(qp + j * 8));
    }
    issueKV(0, 0); CP_COMMIT();
    __syncthreads();

    uint32_t QF[4][4];
#pragma unroll
    for (int t = 0; t < 4; ++t) {
        const int r = wid * 16 + (g & 1) * 8 + (lane & 7);
        const int cb = t * 32 + (g >> 1) * 16;
        ldsm_x4(Qb + sw128((uint32_t)(r * 128 + cb)), QF[t]);
    }

    float Oa[8][4];
#pragma unroll
    for (int nt = 0; nt < 8; ++nt)
#pragma unroll
        for (int c = 0; c < 4; ++c) Oa[nt][c] = 0.f;
    float lacc[4] = {0.f, 0.f, 0.f, 0.f};
    float m_run[2] = {-INFINITY, -INFINITY};

    for (int kt = 0; kt < SEQ / 64; ++kt) {
        __syncthreads();
        if (kt + 1 < SEQ / 64) issueKV((kt + 1) & 1, kt + 1);
        CP_COMMIT();
        CP_WAIT1();
        __syncthreads();

        const uint32_t Kb = Qb + 16384u + (uint32_t)(kt & 1) * 16384u;
        const uint32_t Vb = Kb + 8192u;

        float sacc[8][4];
#pragma unroll
        for (int nt = 0; nt < 8; ++nt)
#pragma unroll
            for (int c = 0; c < 4; ++c) sacc[nt][c] = 0.f;

#pragma unroll
        for (int t = 0; t < 4; ++t) {
#pragma unroll
            for (int pr = 0; pr < 4; ++pr) {
                const int r = pr * 16 + (g >> 1) * 8 + (lane & 7);
                const int cb = t * 32 + (g & 1) * 16;
                uint32_t tt[4];
                ldsm_x4(Kb + sw128((uint32_t)(r * 128 + cb)), tt);
                mma16816(sacc[pr * 2 + 0], QF[t], tt);
                mma16816(sacc[pr * 2 + 1], QF[t], tt + 2);
            }
        }

        float fexp[2];
#pragma unroll
        for (int ri = 0; ri < 2; ++ri) {
            float mx = sacc[0][ri * 2];
#pragma unroll
            for (int nt = 0; nt < 8; ++nt) {
                mx = fmaxf(mx, sacc[nt][ri * 2]);
                mx = fmaxf(mx, sacc[nt][ri * 2 + 1]);
            }
            mx = fmaxf(mx, __shfl_xor_sync(FULL, mx, 1));
            mx = fmaxf(mx, __shfl_xor_sync(FULL, mx, 2));
            const float mn = fmaxf(m_run[ri], mx);
            fexp[ri] = exp2f((m_run[ri] - mn) * SM_SCL);
            m_run[ri] = mn;
        }
        const float negm0 = -m_run[0] * SM_SCL;
        const float negm1 = -m_run[1] * SM_SCL;

        uint32_t P0[8], P1[8];
#pragma unroll
        for (int nt = 0; nt < 8; ++nt) {
            __half2 d0 = __floats2half2_rn(fmaf(sacc[nt][0], SM_SCL, negm0),
                                           fmaf(sacc[nt][1], SM_SCL, negm0));
            __half2 d1 = __floats2half2_rn(fmaf(sacc[nt][2], SM_SCL, negm1),
                                           fmaf(sacc[nt][3], SM_SCL, negm1));
            P0[nt] = h2u(h2exp2(d0));
            P1[nt] = h2u(h2exp2(d1));
        }

#pragma unroll
        for (int nt = 0; nt < 8; ++nt)
#pragma unroll
            for (int c = 0; c < 4; ++c)
                Oa[nt][c] *= fexp[c >> 1];
        lacc[0] *= fexp[0]; lacc[1] *= fexp[0];
        lacc[2] *= fexp[1]; lacc[3] *= fexp[1];

#pragma unroll
        for (int k2 = 0; k2 < 4; ++k2) {
            uint32_t pa[4];
            pa[0] = P0[2 * k2];     pa[1] = P1[2 * k2];
            pa[2] = P0[2 * k2 + 1]; pa[3] = P1[2 * k2 + 1];
            mma16816(lacc, pa, ONES);
#pragma unroll
            for (int npr = 0; npr < 4; ++npr) {
                const int r = k2 * 16 + (g & 1) * 8 + (lane & 7);
                const int cb = npr * 32 + (g >> 1) * 16;
                uint32_t tt[4];
                ldsm_x4_t(Vb + sw128((uint32_t)(r * 128 + cb)), tt);
                mma16816(Oa[npr * 2 + 0], pa, tt);
                mma16816(Oa[npr * 2 + 1], pa, tt + 2);
            }
        }
    }

#pragma unroll
    for (int ri = 0; ri < 2; ++ri) {
        const int row = q0 + wid * 16 + ri * 8 + (lane >> 2);
        const float inv = 1.f / lacc[ri * 2];
#pragma unroll
        for (int nt = 0; nt < 8; ++nt) {
            const int col = nt * 8 + (lane & 3) * 2;
            *(__half2*)(o + (tb + row) * EMB + hh * HD + col) =
                __floats2half2_rn(Oa[nt][ri * 2 + 0] * inv,
                                  Oa[nt][ri * 2 + 1] * inv);
        }
    }
}

// ---------------- launch ----------------
extern "C" void kernel_launch(void* const* d_in, const int* in_sizes, int n_in,
                              void* d_out, int out_size)
{
    const float* x      = (const float*)d_in[0];
    const float* ln1_g  = (const float*)d_in[1];
    const float* ln1_b  = (const float*)d_in[2];
    const float* ln2_g  = (const float*)d_in[3];
    const float* ln2_b  = (const float*)d_in[4];
    const float* w_qkv  = (const float*)d_in[5];
    const float* b_qkv  = (const float*)d_in[6];
    const float* w_proj = (const float*)d_in[7];
    const float* b_proj = (const float*)d_in[8];
    const float* w_fc1  = (const float*)d_in[9];
    const float* b_fc1  = (const float*)d_in[10];
    const float* w_fc2  = (const float*)d_in[11];
    const float* b_fc2  = (const float*)d_in[12];
    float* out = (float*)d_out;

    void *p_h16, *p_qkv16, *p_o16, *p_act16, *p_x1;
    void *p_wq, *p_wp, *p_w1, *p_w2;
    cudaGetSymbolAddress(&p_h16, g_h16);
    cudaGetSymbolAddress(&p_qkv16, g_qkv16);
    cudaGetSymbolAddress(&p_o16, g_o16);
    cudaGetSymbolAddress(&p_act16, g_act16);
    cudaGetSymbolAddress(&p_x1, g_x1);
    cudaGetSymbolAddress(&p_wq, g_wq16);
    cudaGetSymbolAddress(&p_wp, g_wp16);
    cudaGetSymbolAddress(&p_w1, g_w116);
    cudaGetSymbolAddress(&p_w2, g_w216);
    __half* h16   = (__half*)p_h16;
    __half* qkv16 = (__half*)p_qkv16;
    __half* o16   = (__half*)p_o16;
    __half* act16 = (__half*)p_act16;
    float*  x1    = (float*)p_x1;
    __half* wq16  = (__half*)p_wq;
    __half* wp16  = (__half*)p_wp;
    __half* w116  = (__half*)p_w1;
    __half* w216  = (__half*)p_w2;

    cudaFuncSetAttribute((const void*)hgemm<0, 3 * EMB, EMB>,
                         cudaFuncAttributeMaxDynamicSharedMemorySize, GEMM_SMEM);
    cudaFuncSetAttribute((const void*)hgemm<2, EMB, EMB>,
                         cudaFuncAttributeMaxDynamicSharedMemorySize, GEMM_SMEM);
    cudaFuncSetAttribute((const void*)hgemm<1, MLP, EMB>,
                         cudaFuncAttributeMaxDynamicSharedMemorySize, GEMM_SMEM);
    cudaFuncSetAttribute((const void*)hgemm<2, EMB, MLP>,
                         cudaFuncAttributeMaxDynamicSharedMemorySize, GEMM_SMEM);
    cudaFuncSetAttribute(attn_mma, cudaFuncAttributeMaxDynamicSharedMemorySize, ATT_SMEM);

    // 0. weight f2h + LN1 in one launch
    prep_kernel<<<6144 + TOK, 256>>>(w_qkv, wq16, w_proj, wp16, w_fc1, w116,
                                     w_fc2, w216, x, h16, ln1_g, ln1_b);
    // 1. QKV (fp16 out)
    hgemm<0, 3 * EMB, EMB><<<dim3(3 * EMB / 128, TOK / 128), 256, GEMM_SMEM>>>(
        h16, wq16, b_qkv, nullptr, qkv16);
    // 2. attention (fp16 in/out)
    attn_mma<<<dim3(2 * NH, SEQ / 128), 256, ATT_SMEM>>>(qkv16, o16);
    // 3. proj + residual (fp32 out)
    hgemm<2, EMB, EMB><<<dim3(EMB / 128, TOK / 128), 256, GEMM_SMEM>>>(
        o16, wp16, b_proj, x, x1);
    // 4. LN2 -> h16
    ln_kernel<<<TOK, 256>>>(x1, h16, ln2_g, ln2_b);
    // 5. FC1 + GELU (fp16 out)
    hgemm<1, MLP, EMB><<<dim3(MLP / 128, TOK / 128), 256, GEMM_SMEM>>>(
        h16, w116, b_fc1, nullptr, act16);
    // 6. FC2 + residual (fp32 out)
    hgemm<2, EMB, MLP><<<dim3(EMB / 128, TOK / 128), 256, GEMM_SMEM>>>(
        act16, w216, b_fc2, x1, out);
}